// round 1
// baseline (speedup 1.0000x reference)
#include <cuda_runtime.h>

// Problem constants (fixed by the dataset)
#define NN   50000
#define EE   800000
#define ET   (NN + EE)        // edges + self loops = 850000
#define FIN  100
#define W1C  128              // heads*hid = 4*32
#define HEADS 4
#define HID  32
#define FOUT 47
#define NEG  0.2f
#define BNEPS 1e-5f

// ---------------- scratch (device globals: allocation-free) ----------------
__device__ float    g_bufA[(size_t)NN * W1C];   // xl
__device__ float    g_bufB[(size_t)NN * W1C];   // xr
__device__ float    g_bufC[(size_t)NN * W1C];   // h (layer1 out / layer2 in+res)
__device__ float    g_bufD[(size_t)NN * W1C];   // h2
__device__ float    g_e[(size_t)ET * HEADS];    // per-edge logits / exp
__device__ unsigned g_m[(size_t)NN * HEADS];    // encoded segment max
__device__ float    g_den[(size_t)NN * HEADS];  // softmax denominators

// ---------------- helpers ----------------
__device__ __forceinline__ unsigned enc_f(float f) {
    unsigned u = (unsigned)__float_as_int(f);
    return (u & 0x80000000u) ? ~u : (u ^ 0x80000000u);
}
__device__ __forceinline__ float dec_f(unsigned u) {
    unsigned i = (u & 0x80000000u) ? (u ^ 0x80000000u) : ~u;
    return __int_as_float((int)i);
}

__global__ void init_md(unsigned* __restrict__ m, float* __restrict__ den, int n) {
    int i = blockIdx.x * blockDim.x + threadIdx.x;
    if (i < n) { m[i] = 0u; den[i] = 0.f; }   // 0 < enc(-inf)=0x007FFFFF < enc(any finite)
}

__global__ void copy_k(const float* __restrict__ a, float* __restrict__ b, int n) {
    int i = blockIdx.x * blockDim.x + threadIdx.x;
    if (i < n) b[i] = a[i];
}

// ---------------- SGEMM: C[M,ldc] = A[M,K] @ B[K,Ncols] (+bias1+bias2) ----------------
template<int BM, int BN, int BK, int TM, int TN>
__global__ void sgemm_bias(const float* __restrict__ A, const float* __restrict__ B,
                           const float* __restrict__ bias1, const float* __restrict__ bias2,
                           float* __restrict__ C,
                           int M, int K, int Ncols, int ldc)
{
    constexpr int THREADS = (BM / TM) * (BN / TN);
    __shared__ float As[BK][BM];   // stored transposed: As[k][m]
    __shared__ float Bs[BK][BN];

    const int brow = blockIdx.y * BM;
    const int bcol = blockIdx.x * BN;
    const int tid  = threadIdx.x;
    const int tcols = BN / TN;
    const int tc = tid % tcols;
    const int tr = tid / tcols;

    float acc[TM][TN];
#pragma unroll
    for (int i = 0; i < TM; i++)
#pragma unroll
        for (int j = 0; j < TN; j++) acc[i][j] = 0.f;

    for (int k0 = 0; k0 < K; k0 += BK) {
#pragma unroll
        for (int i = tid; i < BM * BK; i += THREADS) {
            int m = i / BK, k = i % BK;
            int gr = brow + m, gk = k0 + k;
            As[k][m] = (gr < M && gk < K) ? A[(size_t)gr * K + gk] : 0.f;
        }
#pragma unroll
        for (int i = tid; i < BK * BN; i += THREADS) {
            int k = i / BN, n = i % BN;
            int gk = k0 + k, gn = bcol + n;
            Bs[k][n] = (gk < K && gn < Ncols) ? B[(size_t)gk * Ncols + gn] : 0.f;
        }
        __syncthreads();
#pragma unroll
        for (int k = 0; k < BK; k++) {
            float a[TM], b[TN];
#pragma unroll
            for (int i = 0; i < TM; i++) a[i] = As[k][tr * TM + i];
#pragma unroll
            for (int j = 0; j < TN; j++) b[j] = Bs[k][tc * TN + j];
#pragma unroll
            for (int i = 0; i < TM; i++)
#pragma unroll
                for (int j = 0; j < TN; j++)
                    acc[i][j] += a[i] * b[j];
        }
        __syncthreads();
    }

#pragma unroll
    for (int i = 0; i < TM; i++) {
        int gr = brow + tr * TM + i;
        if (gr >= M) continue;
#pragma unroll
        for (int j = 0; j < TN; j++) {
            int gn = bcol + tc * TN + j;
            if (gn >= Ncols) continue;
            float v = acc[i][j];
            if (bias1) v += bias1[gn];
            if (bias2) v += bias2[gn];
            C[(size_t)gr * ldc + gn] = v;
        }
    }
}

// ---------------- edge logits (4 heads x 32 ch), warp per edge ----------------
__global__ void edge_logits4(const float* __restrict__ xl, const float* __restrict__ xr,
                             const int* __restrict__ ei, const float* __restrict__ att,
                             float* __restrict__ e, unsigned* __restrict__ m)
{
    int gw   = (blockIdx.x * blockDim.x + threadIdx.x) >> 5;
    int lane = threadIdx.x & 31;
    if (gw >= ET) return;
    int s, d;
    if (gw < EE) { s = ei[gw]; d = ei[EE + gw]; } else { s = d = gw - EE; }

    const float* xls = xl + (size_t)s * W1C;
    const float* xrd = xr + (size_t)d * W1C;
    float sums[HEADS];
#pragma unroll
    for (int h = 0; h < HEADS; h++) {
        float v = xls[h * 32 + lane] + xrd[h * 32 + lane];
        v = (v > 0.f) ? v : NEG * v;
        v *= att[h * 32 + lane];
#pragma unroll
        for (int o = 16; o; o >>= 1) v += __shfl_xor_sync(0xffffffffu, v, o);
        sums[h] = v;
    }
    if (lane == 0) {
#pragma unroll
        for (int h = 0; h < HEADS; h++) {
            e[(size_t)gw * HEADS + h] = sums[h];
            atomicMax(&m[d * HEADS + h], enc_f(sums[h]));
        }
    }
}

__global__ void edge_exp4(float* __restrict__ e, const unsigned* __restrict__ m,
                          float* __restrict__ den, const int* __restrict__ ei)
{
    int idx = blockIdx.x * blockDim.x + threadIdx.x;
    if (idx >= ET * HEADS) return;
    int gw = idx >> 2, h = idx & 3;
    int d = (gw < EE) ? ei[EE + gw] : gw - EE;
    float ex = expf(e[idx] - dec_f(m[d * HEADS + h]));
    e[idx] = ex;
    atomicAdd(&den[d * HEADS + h], ex);
}

__global__ void agg4(const float* __restrict__ e, const float* __restrict__ den,
                     const float* __restrict__ xl, const int* __restrict__ ei,
                     float* __restrict__ out)
{
    int gw   = (blockIdx.x * blockDim.x + threadIdx.x) >> 5;
    int lane = threadIdx.x & 31;
    if (gw >= ET) return;
    int s, d;
    if (gw < EE) { s = ei[gw]; d = ei[EE + gw]; } else { s = d = gw - EE; }
    const float* xls = xl + (size_t)s * W1C;
    float* od = out + (size_t)d * W1C;
#pragma unroll
    for (int h = 0; h < HEADS; h++) {
        float alpha = e[(size_t)gw * HEADS + h] / den[d * HEADS + h];
        atomicAdd(&od[h * 32 + lane], alpha * xls[h * 32 + lane]);
    }
}

// ---------------- edge ops for layer 3 (heads=1, 47 channels) ----------------
__global__ void edge_logits1(const float* __restrict__ xl, const float* __restrict__ xr,
                             const int* __restrict__ ei, const float* __restrict__ att,
                             float* __restrict__ e, unsigned* __restrict__ m)
{
    int gw   = (blockIdx.x * blockDim.x + threadIdx.x) >> 5;
    int lane = threadIdx.x & 31;
    if (gw >= ET) return;
    int s, d;
    if (gw < EE) { s = ei[gw]; d = ei[EE + gw]; } else { s = d = gw - EE; }

    float v = 0.f;
    {
        int c = lane;
        if (c < FOUT) {
            float t = xl[(size_t)s * FOUT + c] + xr[(size_t)d * FOUT + c];
            t = (t > 0.f) ? t : NEG * t;
            v += t * att[c];
        }
        c = lane + 32;
        if (c < FOUT) {
            float t = xl[(size_t)s * FOUT + c] + xr[(size_t)d * FOUT + c];
            t = (t > 0.f) ? t : NEG * t;
            v += t * att[c];
        }
    }
#pragma unroll
    for (int o = 16; o; o >>= 1) v += __shfl_xor_sync(0xffffffffu, v, o);
    if (lane == 0) {
        e[gw] = v;
        atomicMax(&m[d], enc_f(v));
    }
}

__global__ void edge_exp1(float* __restrict__ e, const unsigned* __restrict__ m,
                          float* __restrict__ den, const int* __restrict__ ei)
{
    int gw = blockIdx.x * blockDim.x + threadIdx.x;
    if (gw >= ET) return;
    int d = (gw < EE) ? ei[EE + gw] : gw - EE;
    float ex = expf(e[gw] - dec_f(m[d]));
    e[gw] = ex;
    atomicAdd(&den[d], ex);
}

__global__ void agg1(const float* __restrict__ e, const float* __restrict__ den,
                     const float* __restrict__ xl, const int* __restrict__ ei,
                     float* __restrict__ out)
{
    int gw   = (blockIdx.x * blockDim.x + threadIdx.x) >> 5;
    int lane = threadIdx.x & 31;
    if (gw >= ET) return;
    int s, d;
    if (gw < EE) { s = ei[gw]; d = ei[EE + gw]; } else { s = d = gw - EE; }
    float alpha = e[gw] / den[d];
    for (int c = lane; c < FOUT; c += 32)
        atomicAdd(&out[(size_t)d * FOUT + c], alpha * xl[(size_t)s * FOUT + c]);
}

// ---------------- batchnorm (+ optional relu), in place ----------------
__global__ void bn_act(float* __restrict__ x, const float* __restrict__ g,
                       const float* __restrict__ b, const float* __restrict__ mean,
                       const float* __restrict__ var, int C, int total, int do_relu)
{
    int i = blockIdx.x * blockDim.x + threadIdx.x;
    if (i >= total) return;
    int c = i % C;
    float v = (x[i] - mean[c]) * rsqrtf(var[c] + BNEPS) * g[c] + b[c];
    if (do_relu) v = fmaxf(v, 0.f);
    x[i] = v;
}

// ---------------- launch ----------------
static inline int cdiv(int a, int b) { return (a + b - 1) / b; }

extern "C" void kernel_launch(void* const* d_in, const int* in_sizes, int n_in,
                              void* d_out, int out_size)
{
    const float* x      = (const float*)d_in[0];
    const int*   ei     = (const int*)  d_in[1];
    const float* w1_src = (const float*)d_in[2];
    const float* w1_dst = (const float*)d_in[3];
    const float* att1   = (const float*)d_in[4];
    const float* b1     = (const float*)d_in[5];
    const float* bn1_g  = (const float*)d_in[6];
    const float* bn1_b  = (const float*)d_in[7];
    const float* bn1_m  = (const float*)d_in[8];
    const float* bn1_v  = (const float*)d_in[9];
    const float* res0_w = (const float*)d_in[10];
    const float* res0_b = (const float*)d_in[11];
    const float* w2_src = (const float*)d_in[12];
    const float* w2_dst = (const float*)d_in[13];
    const float* att2   = (const float*)d_in[14];
    const float* b2     = (const float*)d_in[15];
    const float* bn2_g  = (const float*)d_in[16];
    const float* bn2_b  = (const float*)d_in[17];
    const float* bn2_m  = (const float*)d_in[18];
    const float* bn2_v  = (const float*)d_in[19];
    const float* w3_src = (const float*)d_in[20];
    const float* w3_dst = (const float*)d_in[21];
    const float* att3   = (const float*)d_in[22];
    const float* b3     = (const float*)d_in[23];
    const float* bn3_g  = (const float*)d_in[24];
    const float* bn3_b  = (const float*)d_in[25];
    const float* bn3_m  = (const float*)d_in[26];
    const float* bn3_v  = (const float*)d_in[27];
    const float* res2_w = (const float*)d_in[28];
    const float* res2_b = (const float*)d_in[29];
    float* out = (float*)d_out;

    float *bufA, *bufB, *bufC, *bufD, *ebuf, *den;
    unsigned* mbuf;
    cudaGetSymbolAddress((void**)&bufA, g_bufA);
    cudaGetSymbolAddress((void**)&bufB, g_bufB);
    cudaGetSymbolAddress((void**)&bufC, g_bufC);
    cudaGetSymbolAddress((void**)&bufD, g_bufD);
    cudaGetSymbolAddress((void**)&ebuf, g_e);
    cudaGetSymbolAddress((void**)&mbuf, g_m);
    cudaGetSymbolAddress((void**)&den,  g_den);

    const int EB = 256;                       // edge kernels block size
    const int WPB = EB / 32;                  // warps (edges) per block
    const int eblocks = cdiv(ET, WPB);

    dim3 g128(1, cdiv(NN, 64));               // BN=128 covers 128 cols
    dim3 g64 (1, cdiv(NN, 64));               // BN=64 covers 47 cols

    // ===== layer 1 =====
    sgemm_bias<64,128,32,8,4><<<g128, 256>>>(x, w1_src, nullptr, nullptr, bufA, NN, FIN, W1C, W1C);
    sgemm_bias<64,128,32,8,4><<<g128, 256>>>(x, w1_dst, nullptr, nullptr, bufB, NN, FIN, W1C, W1C);
    sgemm_bias<64,128,32,8,4><<<g128, 256>>>(x, res0_w, res0_b, b1,      bufC, NN, FIN, W1C, W1C);
    init_md<<<cdiv(NN*HEADS, 256), 256>>>(mbuf, den, NN * HEADS);
    edge_logits4<<<eblocks, EB>>>(bufA, bufB, ei, att1, ebuf, mbuf);
    edge_exp4<<<cdiv(ET*HEADS, 256), 256>>>(ebuf, mbuf, den, ei);
    agg4<<<eblocks, EB>>>(ebuf, den, bufA, ei, bufC);
    bn_act<<<cdiv(NN*W1C, 256), 256>>>(bufC, bn1_g, bn1_b, bn1_m, bn1_v, W1C, NN * W1C, 1);

    // ===== layer 2 =====
    sgemm_bias<64,128,32,8,4><<<g128, 256>>>(bufC, w2_src, nullptr, nullptr, bufA, NN, W1C, W1C, W1C);
    sgemm_bias<64,128,32,8,4><<<g128, 256>>>(bufC, w2_dst, nullptr, nullptr, bufB, NN, W1C, W1C, W1C);
    copy_k<<<cdiv(NN*W1C, 256), 256>>>(bufC, bufD, NN * W1C);   // identity residual (+b2=0)
    init_md<<<cdiv(NN*HEADS, 256), 256>>>(mbuf, den, NN * HEADS);
    edge_logits4<<<eblocks, EB>>>(bufA, bufB, ei, att2, ebuf, mbuf);
    edge_exp4<<<cdiv(ET*HEADS, 256), 256>>>(ebuf, mbuf, den, ei);
    agg4<<<eblocks, EB>>>(ebuf, den, bufA, ei, bufD);
    bn_act<<<cdiv(NN*W1C, 256), 256>>>(bufD, bn2_g, bn2_b, bn2_m, bn2_v, W1C, NN * W1C, 1);

    // ===== layer 3 (heads=1, 47 out) =====
    sgemm_bias<64,64,32,8,4><<<g64, 128>>>(bufD, w3_src, nullptr, nullptr, bufA, NN, W1C, FOUT, FOUT);
    sgemm_bias<64,64,32,8,4><<<g64, 128>>>(bufD, w3_dst, nullptr, nullptr, bufB, NN, W1C, FOUT, FOUT);
    sgemm_bias<64,64,32,8,4><<<g64, 128>>>(bufD, res2_w, res2_b, b3,      out,  NN, W1C, FOUT, FOUT);
    init_md<<<cdiv(NN, 256), 256>>>(mbuf, den, NN);
    edge_logits1<<<eblocks, EB>>>(bufA, bufB, ei, att3, ebuf, mbuf);
    edge_exp1<<<cdiv(ET, 256), 256>>>(ebuf, mbuf, den, ei);
    agg1<<<eblocks, EB>>>(ebuf, den, bufA, ei, out);
    bn_act<<<cdiv(NN*FOUT, 256), 256>>>(out, bn3_g, bn3_b, bn3_m, bn3_v, FOUT, NN * FOUT, 0);
}

// round 2
// speedup vs baseline: 1.3401x; 1.3401x over previous
#include <cuda_runtime.h>

// Problem constants (fixed by the dataset)
#define NN   50000
#define EE   800000
#define FIN  100
#define W1C  128              // heads*hid = 4*32
#define HEADS 4
#define HID  32
#define FOUT 47
#define NEG  0.2f
#define BNEPS 1e-5f

// ---------------- scratch (device globals: allocation-free) ----------------
__device__ float g_bufA[(size_t)NN * W1C];   // xl
__device__ float g_bufB[(size_t)NN * W1C];   // xr
__device__ float g_bufC[(size_t)NN * W1C];   // h / residual
__device__ float g_bufD[(size_t)NN * W1C];   // h2
__device__ int   g_deg[NN];
__device__ int   g_rowptr[NN + 1];
__device__ int   g_pos[NN];
__device__ int   g_adj[EE];

// ---------------- CSR build (dst-grouped) ----------------
__global__ void zero_deg() {
    int i = blockIdx.x * blockDim.x + threadIdx.x;
    if (i < NN) g_deg[i] = 0;
}

__global__ void hist_dst(const int* __restrict__ ei) {
    int i = blockIdx.x * blockDim.x + threadIdx.x;
    if (i < EE) atomicAdd(&g_deg[ei[EE + i]], 1);
}

__global__ void scan_deg() {
    __shared__ int ssum[1024];
    const int CH = 49;                      // 49 * 1024 = 50176 >= NN
    int t = threadIdx.x;
    int base = t * CH;
    int s = 0;
#pragma unroll 1
    for (int i = 0; i < CH; i++) {
        int idx = base + i;
        if (idx < NN) s += g_deg[idx];
    }
    ssum[t] = s;
    __syncthreads();
    for (int off = 1; off < 1024; off <<= 1) {
        int v = (t >= off) ? ssum[t - off] : 0;
        __syncthreads();
        ssum[t] += v;
        __syncthreads();
    }
    int run = (t == 0) ? 0 : ssum[t - 1];
#pragma unroll 1
    for (int i = 0; i < CH; i++) {
        int idx = base + i;
        if (idx < NN) {
            g_rowptr[idx] = run;
            g_pos[idx]    = run;
            run += g_deg[idx];
        }
    }
    if (t == 0) g_rowptr[NN] = EE;
}

__global__ void scatter_edges(const int* __restrict__ ei) {
    int i = blockIdx.x * blockDim.x + threadIdx.x;
    if (i >= EE) return;
    int s = ei[i];
    int d = ei[EE + i];
    int p = atomicAdd(&g_pos[d], 1);
    g_adj[p] = s;
}

// ---------------- SGEMM: C[M,ldc] = A[M,K] @ B[K,Ncols] (+bias1+bias2) ----------------
template<int BM, int BN, int BK, int TM, int TN>
__global__ void sgemm_bias(const float* __restrict__ A, const float* __restrict__ B,
                           const float* __restrict__ bias1, const float* __restrict__ bias2,
                           float* __restrict__ C,
                           int M, int K, int Ncols, int ldc)
{
    constexpr int THREADS = (BM / TM) * (BN / TN);
    __shared__ float As[BK][BM];   // transposed: As[k][m]
    __shared__ float Bs[BK][BN];

    const int brow = blockIdx.y * BM;
    const int bcol = blockIdx.x * BN;
    const int tid  = threadIdx.x;
    const int tcols = BN / TN;
    const int tc = tid % tcols;
    const int tr = tid / tcols;

    float acc[TM][TN];
#pragma unroll
    for (int i = 0; i < TM; i++)
#pragma unroll
        for (int j = 0; j < TN; j++) acc[i][j] = 0.f;

    for (int k0 = 0; k0 < K; k0 += BK) {
#pragma unroll
        for (int i = tid; i < BM * BK; i += THREADS) {
            int m = i / BK, k = i % BK;
            int gr = brow + m, gk = k0 + k;
            As[k][m] = (gr < M && gk < K) ? A[(size_t)gr * K + gk] : 0.f;
        }
#pragma unroll
        for (int i = tid; i < BK * BN; i += THREADS) {
            int k = i / BN, n = i % BN;
            int gk = k0 + k, gn = bcol + n;
            Bs[k][n] = (gk < K && gn < Ncols) ? B[(size_t)gk * Ncols + gn] : 0.f;
        }
        __syncthreads();
#pragma unroll
        for (int k = 0; k < BK; k++) {
            float a[TM], b[TN];
#pragma unroll
            for (int i = 0; i < TM; i++) a[i] = As[k][tr * TM + i];
#pragma unroll
            for (int j = 0; j < TN; j++) b[j] = Bs[k][tc * TN + j];
#pragma unroll
            for (int i = 0; i < TM; i++)
#pragma unroll
                for (int j = 0; j < TN; j++)
                    acc[i][j] += a[i] * b[j];
        }
        __syncthreads();
    }

#pragma unroll
    for (int i = 0; i < TM; i++) {
        int gr = brow + tr * TM + i;
        if (gr >= M) continue;
#pragma unroll
        for (int j = 0; j < TN; j++) {
            int gn = bcol + tc * TN + j;
            if (gn >= Ncols) continue;
            float v = acc[i][j];
            if (bias1) v += bias1[gn];
            if (bias2) v += bias2[gn];
            C[(size_t)gr * ldc + gn] = v;
        }
    }
}

// ---------------- fused node kernel: 4 heads x 32 ch ----------------
// One block (128 threads) per destination node. Online softmax over incoming
// edges (incl. self loop), then +bias +residual, BN, optional relu.
__global__ void __launch_bounds__(128)
gat_node4(const float* __restrict__ xl, const float* __restrict__ xr,
          const float* __restrict__ res, const float* __restrict__ att,
          const float* __restrict__ bias,
          const float* __restrict__ bng, const float* __restrict__ bnb,
          const float* __restrict__ bnm, const float* __restrict__ bnv,
          float* __restrict__ outbuf, int do_relu)
{
    int d   = blockIdx.x;
    int tid = threadIdx.x;   // channel = head*32 + lane

    float xrv  = xr[(size_t)d * W1C + tid];
    float attv = att[tid];

    int beg = g_rowptr[d], end = g_rowptr[d + 1];

    float m = -3.0e38f, denom = 0.f, acc = 0.f;

    for (int j = beg - 1; j < end; j++) {        // j==beg-1 -> self loop
        int s = (j < beg) ? d : g_adj[j];
        float xls = xl[(size_t)s * W1C + tid];
        float v = xls + xrv;
        v = (v > 0.f) ? v : NEG * v;
        v *= attv;
#pragma unroll
        for (int o = 16; o; o >>= 1) v += __shfl_xor_sync(0xffffffffu, v, o);
        float mn = fmaxf(m, v);
        float sc = __expf(m - mn);
        float w  = __expf(v - mn);
        denom = denom * sc + w;
        acc   = acc * sc + w * xls;
        m = mn;
    }

    float val = acc / denom;
    if (bias) val += bias[tid];
    val += res[(size_t)d * W1C + tid];
    val = (val - bnm[tid]) * rsqrtf(bnv[tid] + BNEPS) * bng[tid] + bnb[tid];
    if (do_relu) val = fmaxf(val, 0.f);
    outbuf[(size_t)d * W1C + tid] = val;
}

// ---------------- fused node kernel: 1 head x 47 ch (warp per node) ----------------
__global__ void __launch_bounds__(256)
gat_node1(const float* __restrict__ xl, const float* __restrict__ xr,
          const float* __restrict__ res, const float* __restrict__ att,
          const float* __restrict__ bng, const float* __restrict__ bnb,
          const float* __restrict__ bnm, const float* __restrict__ bnv,
          float* __restrict__ outbuf)
{
    int d    = (blockIdx.x * blockDim.x + threadIdx.x) >> 5;
    int lane = threadIdx.x & 31;
    if (d >= NN) return;

    int c0 = lane;
    int c1 = lane + 32;
    bool has1 = (c1 < FOUT);

    float xr0 = xr[(size_t)d * FOUT + c0];
    float xr1 = has1 ? xr[(size_t)d * FOUT + c1] : 0.f;
    float a0  = att[c0];
    float a1  = has1 ? att[c1] : 0.f;

    int beg = g_rowptr[d], end = g_rowptr[d + 1];

    float m = -3.0e38f, denom = 0.f, acc0 = 0.f, acc1 = 0.f;

    for (int j = beg - 1; j < end; j++) {
        int s = (j < beg) ? d : g_adj[j];
        float x0 = xl[(size_t)s * FOUT + c0];
        float x1 = has1 ? xl[(size_t)s * FOUT + c1] : 0.f;
        float t0 = x0 + xr0; t0 = (t0 > 0.f) ? t0 : NEG * t0;
        float t1 = x1 + xr1; t1 = (t1 > 0.f) ? t1 : NEG * t1;
        float v = t0 * a0 + t1 * a1;
#pragma unroll
        for (int o = 16; o; o >>= 1) v += __shfl_xor_sync(0xffffffffu, v, o);
        float mn = fmaxf(m, v);
        float sc = __expf(m - mn);
        float w  = __expf(v - mn);
        denom = denom * sc + w;
        acc0  = acc0 * sc + w * x0;
        acc1  = acc1 * sc + w * x1;
        m = mn;
    }

    float inv = 1.f / denom;
    {
        float val = acc0 * inv + res[(size_t)d * FOUT + c0];
        val = (val - bnm[c0]) * rsqrtf(bnv[c0] + BNEPS) * bng[c0] + bnb[c0];
        outbuf[(size_t)d * FOUT + c0] = val;
    }
    if (has1) {
        float val = acc1 * inv + res[(size_t)d * FOUT + c1];
        val = (val - bnm[c1]) * rsqrtf(bnv[c1] + BNEPS) * bng[c1] + bnb[c1];
        outbuf[(size_t)d * FOUT + c1] = val;
    }
}

// ---------------- launch ----------------
static inline int cdiv(int a, int b) { return (a + b - 1) / b; }

extern "C" void kernel_launch(void* const* d_in, const int* in_sizes, int n_in,
                              void* d_out, int out_size)
{
    const float* x      = (const float*)d_in[0];
    const int*   ei     = (const int*)  d_in[1];
    const float* w1_src = (const float*)d_in[2];
    const float* w1_dst = (const float*)d_in[3];
    const float* att1   = (const float*)d_in[4];
    const float* b1     = (const float*)d_in[5];
    const float* bn1_g  = (const float*)d_in[6];
    const float* bn1_b  = (const float*)d_in[7];
    const float* bn1_m  = (const float*)d_in[8];
    const float* bn1_v  = (const float*)d_in[9];
    const float* res0_w = (const float*)d_in[10];
    const float* res0_b = (const float*)d_in[11];
    const float* w2_src = (const float*)d_in[12];
    const float* w2_dst = (const float*)d_in[13];
    const float* att2   = (const float*)d_in[14];
    const float* b2     = (const float*)d_in[15];
    const float* bn2_g  = (const float*)d_in[16];
    const float* bn2_b  = (const float*)d_in[17];
    const float* bn2_m  = (const float*)d_in[18];
    const float* bn2_v  = (const float*)d_in[19];
    const float* w3_src = (const float*)d_in[20];
    const float* w3_dst = (const float*)d_in[21];
    const float* att3   = (const float*)d_in[22];
    const float* b3     = (const float*)d_in[23];
    const float* bn3_g  = (const float*)d_in[24];
    const float* bn3_b  = (const float*)d_in[25];
    const float* bn3_m  = (const float*)d_in[26];
    const float* bn3_v  = (const float*)d_in[27];
    const float* res2_w = (const float*)d_in[28];
    const float* res2_b = (const float*)d_in[29];
    float* out = (float*)d_out;

    float *bufA, *bufB, *bufC, *bufD;
    cudaGetSymbolAddress((void**)&bufA, g_bufA);
    cudaGetSymbolAddress((void**)&bufB, g_bufB);
    cudaGetSymbolAddress((void**)&bufC, g_bufC);
    cudaGetSymbolAddress((void**)&bufD, g_bufD);

    // ---- CSR build (dst-grouped) ----
    zero_deg<<<cdiv(NN, 256), 256>>>();
    hist_dst<<<cdiv(EE, 256), 256>>>(ei);
    scan_deg<<<1, 1024>>>();
    scatter_edges<<<cdiv(EE, 256), 256>>>(ei);

    dim3 g128(1, cdiv(NN, 64));
    dim3 g64 (1, cdiv(NN, 64));

    // ===== layer 1 =====
    sgemm_bias<64,128,32,8,4><<<g128, 256>>>(x, w1_src, nullptr, nullptr, bufA, NN, FIN, W1C, W1C);
    sgemm_bias<64,128,32,8,4><<<g128, 256>>>(x, w1_dst, nullptr, nullptr, bufB, NN, FIN, W1C, W1C);
    sgemm_bias<64,128,32,8,4><<<g128, 256>>>(x, res0_w, res0_b, b1,      bufC, NN, FIN, W1C, W1C);
    gat_node4<<<NN, 128>>>(bufA, bufB, bufC, att1, nullptr,
                           bn1_g, bn1_b, bn1_m, bn1_v, bufC, 1);

    // ===== layer 2 (identity residual) =====
    sgemm_bias<64,128,32,8,4><<<g128, 256>>>(bufC, w2_src, nullptr, nullptr, bufA, NN, W1C, W1C, W1C);
    sgemm_bias<64,128,32,8,4><<<g128, 256>>>(bufC, w2_dst, nullptr, nullptr, bufB, NN, W1C, W1C, W1C);
    gat_node4<<<NN, 128>>>(bufA, bufB, bufC, att2, b2,
                           bn2_g, bn2_b, bn2_m, bn2_v, bufD, 1);

    // ===== layer 3 (heads=1, 47 out) =====
    sgemm_bias<64,64,32,8,4><<<g64, 128>>>(bufD, w3_src, nullptr, nullptr, bufA, NN, W1C, FOUT, FOUT);
    sgemm_bias<64,64,32,8,4><<<g64, 128>>>(bufD, w3_dst, nullptr, nullptr, bufB, NN, W1C, FOUT, FOUT);
    sgemm_bias<64,64,32,8,4><<<g64, 128>>>(bufD, res2_w, res2_b, b3,      bufC, NN, W1C, FOUT, FOUT);
    gat_node1<<<cdiv(NN * 32, 256), 256>>>(bufA, bufB, bufC, att3,
                                           bn3_g, bn3_b, bn3_m, bn3_v, out);
}

// round 3
// speedup vs baseline: 2.4217x; 1.8071x over previous
#include <cuda_runtime.h>

// Problem constants (fixed by the dataset)
#define NN   50000
#define EE   800000
#define FIN  100
#define W1C  128              // heads*hid = 4*32
#define HEADS 4
#define HID  32
#define FOUT 47
#define NEG  0.2f
#define BNEPS 1e-5f

#define NC1 384               // packed layer-1 width: xl|xr|res
#define NC2 256               // packed layer-2 width: xl|xr
#define NC3 144               // packed layer-3 width: 48|48|48 (47 + pad each)

// ---------------- scratch (device globals: allocation-free) ----------------
__device__ float g_cat1[(size_t)NN * NC1];
__device__ float g_cat2[(size_t)NN * NC2];
__device__ float g_cat3[(size_t)NN * NC3];
__device__ float g_h1[(size_t)NN * W1C];
__device__ float g_h2[(size_t)NN * W1C];
__device__ float g_w1[(size_t)FIN * NC1];
__device__ float g_w2[(size_t)W1C * NC2];
__device__ float g_w3[(size_t)W1C * NC3];
__device__ float g_bias1[NC1];
__device__ float g_bias2[NC2];
__device__ float g_bias3[NC3];
__device__ int   g_deg[NN];
__device__ int   g_rowptr[NN + 1];
__device__ int   g_pos[NN];
__device__ int   g_adj[EE];

// ---------------- CSR build (dst-grouped) ----------------
__global__ void zero_deg() {
    int i = blockIdx.x * blockDim.x + threadIdx.x;
    if (i < NN) g_deg[i] = 0;
}

__global__ void hist_dst(const int* __restrict__ ei) {
    int i = blockIdx.x * blockDim.x + threadIdx.x;
    if (i < EE) atomicAdd(&g_deg[ei[EE + i]], 1);
}

__global__ void scan_deg() {
    __shared__ int ssum[1024];
    const int CH = 49;                      // 49 * 1024 = 50176 >= NN
    int t = threadIdx.x;
    int base = t * CH;
    int s = 0;
#pragma unroll 1
    for (int i = 0; i < CH; i++) {
        int idx = base + i;
        if (idx < NN) s += g_deg[idx];
    }
    ssum[t] = s;
    __syncthreads();
    for (int off = 1; off < 1024; off <<= 1) {
        int v = (t >= off) ? ssum[t - off] : 0;
        __syncthreads();
        ssum[t] += v;
        __syncthreads();
    }
    int run = (t == 0) ? 0 : ssum[t - 1];
#pragma unroll 1
    for (int i = 0; i < CH; i++) {
        int idx = base + i;
        if (idx < NN) {
            g_rowptr[idx] = run;
            g_pos[idx]    = run;
            run += g_deg[idx];
        }
    }
    if (t == 0) g_rowptr[NN] = EE;
}

__global__ void scatter_edges(const int* __restrict__ ei) {
    int i = blockIdx.x * blockDim.x + threadIdx.x;
    if (i >= EE) return;
    int s = ei[i];
    int d = ei[EE + i];
    int p = atomicAdd(&g_pos[d], 1);
    g_adj[p] = s;
}

// ---------------- weight packing (one kernel) ----------------
// g_w1[k][c]: c<128 -> w1_src, c<256 -> w1_dst, else res0_w
// g_w3[k][c]: 0..46 w3_src, 48..94 w3_dst, 96..142 res2_w, pads zero
__global__ void pack_all(const float* __restrict__ w1s, const float* __restrict__ w1d,
                         const float* __restrict__ r0w, const float* __restrict__ r0b,
                         const float* __restrict__ b1,
                         const float* __restrict__ w2s, const float* __restrict__ w2d,
                         const float* __restrict__ w3s, const float* __restrict__ w3d,
                         const float* __restrict__ r2w, const float* __restrict__ r2b,
                         const float* __restrict__ b3)
{
    const int S1 = FIN * NC1;          // 38400
    const int S2 = W1C * NC2;          // 32768
    const int S3 = W1C * NC3;          // 18432
    int i = blockIdx.x * blockDim.x + threadIdx.x;

    if (i < S1) {
        int k = i / NC1, c = i % NC1;
        float v;
        if (c < 128)      v = w1s[k * 128 + c];
        else if (c < 256) v = w1d[k * 128 + (c - 128)];
        else              v = r0w[k * 128 + (c - 256)];
        g_w1[i] = v;
        return;
    }
    i -= S1;
    if (i < S2) {
        int k = i / NC2, c = i % NC2;
        g_w2[i] = (c < 128) ? w2s[k * 128 + c] : w2d[k * 128 + (c - 128)];
        return;
    }
    i -= S2;
    if (i < S3) {
        int k = i / NC3, c = i % NC3;
        float v = 0.f;
        if (c < 47)                     v = w3s[k * 47 + c];
        else if (c >= 48 && c < 95)     v = w3d[k * 47 + (c - 48)];
        else if (c >= 96 && c < 143)    v = r2w[k * 47 + (c - 96)];
        g_w3[i] = v;
        return;
    }
    i -= S3;
    if (i < NC1) { g_bias1[i] = (i >= 256) ? (r0b[i - 256] + b1[i - 256]) : 0.f; return; }
    i -= NC1;
    if (i < NC2) { g_bias2[i] = 0.f; return; }
    i -= NC2;
    if (i < NC3) {
        g_bias3[i] = (i >= 96 && i < 143) ? (r2b[i - 96] + b3[i - 96]) : 0.f;
        return;
    }
}

// ---------------- SGEMM: C[M,N] = A[M,K] @ B[K,N] + bias, 128x128x16, 8x8 ----------------
template<int BM, int BN, int BK, int TM, int TN>
__global__ void __launch_bounds__(256)
sgemm_pack(const float* __restrict__ A, const float* __restrict__ B,
           const float* __restrict__ bias, float* __restrict__ C,
           int M, int K, int N)
{
    __shared__ float As[BK][BM + 4];   // transposed, padded (conflict-free STS)
    __shared__ float Bs[BK][BN];

    const int brow = blockIdx.y * BM;
    const int bcol = blockIdx.x * BN;
    const int tid  = threadIdx.x;
    const int tc = tid % (BN / TN);
    const int tr = tid / (BN / TN);

    // loader mapping
    const int arow = tid >> 2;            // 0..63
    const int ak   = (tid & 3) * 4;       // 0,4,8,12
    const int bk   = tid >> 5;            // 0..7
    const int bn   = (tid & 31) * 4;      // 0..124

    float acc[TM][TN];
#pragma unroll
    for (int i = 0; i < TM; i++)
#pragma unroll
        for (int j = 0; j < TN; j++) acc[i][j] = 0.f;

    for (int k0 = 0; k0 < K; k0 += BK) {
        // ---- load A tile (BM x BK), store transposed ----
#pragma unroll
        for (int h = 0; h < 2; h++) {
            int r  = arow + h * 64;
            int gr = brow + r;
            int gk = k0 + ak;
            float4 v = {0.f, 0.f, 0.f, 0.f};
            if (gr < M) {
                if (gk + 3 < K) {
                    v = *(const float4*)(A + (size_t)gr * K + gk);
                } else {
                    if (gk     < K) v.x = A[(size_t)gr * K + gk];
                    if (gk + 1 < K) v.y = A[(size_t)gr * K + gk + 1];
                    if (gk + 2 < K) v.z = A[(size_t)gr * K + gk + 2];
                }
            }
            As[ak + 0][r] = v.x;
            As[ak + 1][r] = v.y;
            As[ak + 2][r] = v.z;
            As[ak + 3][r] = v.w;
        }
        // ---- load B tile (BK x BN) ----
#pragma unroll
        for (int h = 0; h < 2; h++) {
            int kk = bk + h * 8;
            int gk = k0 + kk;
            int gn = bcol + bn;
            float4 v = {0.f, 0.f, 0.f, 0.f};
            if (gk < K) {
                if (gn + 3 < N) {
                    v = *(const float4*)(B + (size_t)gk * N + gn);
                } else {
                    if (gn     < N) v.x = B[(size_t)gk * N + gn];
                    if (gn + 1 < N) v.y = B[(size_t)gk * N + gn + 1];
                    if (gn + 2 < N) v.z = B[(size_t)gk * N + gn + 2];
                }
            }
            *(float4*)&Bs[kk][bn] = v;
        }
        __syncthreads();

#pragma unroll
        for (int k = 0; k < BK; k++) {
            float a[TM], b[TN];
#pragma unroll
            for (int i = 0; i < TM; i++) a[i] = As[k][tr * TM + i];
#pragma unroll
            for (int j = 0; j < TN; j++) b[j] = Bs[k][tc * TN + j];
#pragma unroll
            for (int i = 0; i < TM; i++)
#pragma unroll
                for (int j = 0; j < TN; j++)
                    acc[i][j] += a[i] * b[j];
        }
        __syncthreads();
    }

    // ---- epilogue: +bias, vectorized stores ----
#pragma unroll
    for (int i = 0; i < TM; i++) {
        int gr = brow + tr * TM + i;
        if (gr >= M) continue;
#pragma unroll
        for (int j = 0; j < TN; j += 4) {
            int gn = bcol + tc * TN + j;
            if (gn + 3 < N) {
                float4 bv = *(const float4*)(bias + gn);
                float4 o;
                o.x = acc[i][j + 0] + bv.x;
                o.y = acc[i][j + 1] + bv.y;
                o.z = acc[i][j + 2] + bv.z;
                o.w = acc[i][j + 3] + bv.w;
                *(float4*)(C + (size_t)gr * N + gn) = o;
            } else {
#pragma unroll
                for (int q = 0; q < 4; q++)
                    if (gn + q < N) C[(size_t)gr * N + gn + q] = acc[i][j + q] + bias[gn + q];
            }
        }
    }
}

// ---------------- fused node kernel: 4 heads x 32 ch, warp per node ----------------
// lane owns channels 4*lane..4*lane+3 (all within head = lane/8).
__global__ void __launch_bounds__(256)
gat_node4v(const float* __restrict__ xlxr, int ldin, int xroff,
           const float* __restrict__ res, int ldres,
           const float* __restrict__ att, const float* __restrict__ bias,
           const float* __restrict__ bng, const float* __restrict__ bnb,
           const float* __restrict__ bnm, const float* __restrict__ bnv,
           float* __restrict__ outbuf, int ldout, int do_relu)
{
    int d    = (blockIdx.x * blockDim.x + threadIdx.x) >> 5;
    int lane = threadIdx.x & 31;
    if (d >= NN) return;
    int c = lane * 4;

    const float4 xr4 = *(const float4*)(xlxr + (size_t)d * ldin + xroff + c);
    const float4 at4 = *(const float4*)(att + c);

    int beg = g_rowptr[d], end = g_rowptr[d + 1];

    float m = -3.0e38f, den = 0.f;
    float4 acc = {0.f, 0.f, 0.f, 0.f};

    for (int j = beg - 1; j < end; j++) {           // j==beg-1 -> self loop
        int s = (j < beg) ? d : g_adj[j];
        float4 xv = *(const float4*)(xlxr + (size_t)s * ldin + c);
        float t0 = xv.x + xr4.x; t0 = (t0 > 0.f) ? t0 : NEG * t0;
        float t1 = xv.y + xr4.y; t1 = (t1 > 0.f) ? t1 : NEG * t1;
        float t2 = xv.z + xr4.z; t2 = (t2 > 0.f) ? t2 : NEG * t2;
        float t3 = xv.w + xr4.w; t3 = (t3 > 0.f) ? t3 : NEG * t3;
        float v = t0 * at4.x + t1 * at4.y + t2 * at4.z + t3 * at4.w;
        v += __shfl_xor_sync(0xffffffffu, v, 1);
        v += __shfl_xor_sync(0xffffffffu, v, 2);
        v += __shfl_xor_sync(0xffffffffu, v, 4);    // 8-lane group = one head
        float mn = fmaxf(m, v);
        float sc = __expf(m - mn);
        float w  = __expf(v - mn);
        den = den * sc + w;
        acc.x = acc.x * sc + w * xv.x;
        acc.y = acc.y * sc + w * xv.y;
        acc.z = acc.z * sc + w * xv.z;
        acc.w = acc.w * sc + w * xv.w;
        m = mn;
    }

    float inv = 1.f / den;
    float4 o;
    o.x = acc.x * inv; o.y = acc.y * inv; o.z = acc.z * inv; o.w = acc.w * inv;
    if (bias) {
        float4 bv = *(const float4*)(bias + c);
        o.x += bv.x; o.y += bv.y; o.z += bv.z; o.w += bv.w;
    }
    float4 rv = *(const float4*)(res + (size_t)d * ldres + c);
    o.x += rv.x; o.y += rv.y; o.z += rv.z; o.w += rv.w;

    float4 mm = *(const float4*)(bnm + c);
    float4 vv = *(const float4*)(bnv + c);
    float4 gg = *(const float4*)(bng + c);
    float4 bb = *(const float4*)(bnb + c);
    o.x = (o.x - mm.x) * rsqrtf(vv.x + BNEPS) * gg.x + bb.x;
    o.y = (o.y - mm.y) * rsqrtf(vv.y + BNEPS) * gg.y + bb.y;
    o.z = (o.z - mm.z) * rsqrtf(vv.z + BNEPS) * gg.z + bb.z;
    o.w = (o.w - mm.w) * rsqrtf(vv.w + BNEPS) * gg.w + bb.w;
    if (do_relu) {
        o.x = fmaxf(o.x, 0.f); o.y = fmaxf(o.y, 0.f);
        o.z = fmaxf(o.z, 0.f); o.w = fmaxf(o.w, 0.f);
    }
    *(float4*)(outbuf + (size_t)d * ldout + c) = o;
}

// ---------------- fused node kernel: 1 head x 47 ch (warp per node) ----------------
// reads packed C3: xl at col 0, xr at col 48, res at col 96 (stride NC3)
__global__ void __launch_bounds__(256)
gat_node1(const float* __restrict__ cat, const float* __restrict__ att,
          const float* __restrict__ bng, const float* __restrict__ bnb,
          const float* __restrict__ bnm, const float* __restrict__ bnv,
          float* __restrict__ outbuf)
{
    int d    = (blockIdx.x * blockDim.x + threadIdx.x) >> 5;
    int lane = threadIdx.x & 31;
    if (d >= NN) return;

    int c0 = lane;
    int c1 = lane + 32;
    bool has1 = (c1 < FOUT);

    const float* rowd = cat + (size_t)d * NC3;
    float xr0 = rowd[48 + c0];
    float xr1 = has1 ? rowd[48 + c1] : 0.f;
    float a0  = att[c0];
    float a1  = has1 ? att[c1] : 0.f;

    int beg = g_rowptr[d], end = g_rowptr[d + 1];

    float m = -3.0e38f, den = 0.f, acc0 = 0.f, acc1 = 0.f;

    for (int j = beg - 1; j < end; j++) {
        int s = (j < beg) ? d : g_adj[j];
        const float* rows = cat + (size_t)s * NC3;
        float x0 = rows[c0];
        float x1 = has1 ? rows[c1] : 0.f;
        float t0 = x0 + xr0; t0 = (t0 > 0.f) ? t0 : NEG * t0;
        float t1 = x1 + xr1; t1 = (t1 > 0.f) ? t1 : NEG * t1;
        float v = t0 * a0 + t1 * a1;
#pragma unroll
        for (int o = 16; o; o >>= 1) v += __shfl_xor_sync(0xffffffffu, v, o);
        float mn = fmaxf(m, v);
        float sc = __expf(m - mn);
        float w  = __expf(v - mn);
        den  = den  * sc + w;
        acc0 = acc0 * sc + w * x0;
        acc1 = acc1 * sc + w * x1;
        m = mn;
    }

    float inv = 1.f / den;
    {
        float val = acc0 * inv + rowd[96 + c0];     // residual (+folded bias)
        val = (val - bnm[c0]) * rsqrtf(bnv[c0] + BNEPS) * bng[c0] + bnb[c0];
        outbuf[(size_t)d * FOUT + c0] = val;
    }
    if (has1) {
        float val = acc1 * inv + rowd[96 + c1];
        val = (val - bnm[c1]) * rsqrtf(bnv[c1] + BNEPS) * bng[c1] + bnb[c1];
        outbuf[(size_t)d * FOUT + c1] = val;
    }
}

// ---------------- launch ----------------
static inline int cdiv(int a, int b) { return (a + b - 1) / b; }

extern "C" void kernel_launch(void* const* d_in, const int* in_sizes, int n_in,
                              void* d_out, int out_size)
{
    const float* x      = (const float*)d_in[0];
    const int*   ei     = (const int*)  d_in[1];
    const float* w1_src = (const float*)d_in[2];
    const float* w1_dst = (const float*)d_in[3];
    const float* att1   = (const float*)d_in[4];
    const float* b1     = (const float*)d_in[5];
    const float* bn1_g  = (const float*)d_in[6];
    const float* bn1_b  = (const float*)d_in[7];
    const float* bn1_m  = (const float*)d_in[8];
    const float* bn1_v  = (const float*)d_in[9];
    const float* res0_w = (const float*)d_in[10];
    const float* res0_b = (const float*)d_in[11];
    const float* w2_src = (const float*)d_in[12];
    const float* w2_dst = (const float*)d_in[13];
    const float* att2   = (const float*)d_in[14];
    const float* b2     = (const float*)d_in[15];
    const float* bn2_g  = (const float*)d_in[16];
    const float* bn2_b  = (const float*)d_in[17];
    const float* bn2_m  = (const float*)d_in[18];
    const float* bn2_v  = (const float*)d_in[19];
    const float* w3_src = (const float*)d_in[20];
    const float* w3_dst = (const float*)d_in[21];
    const float* att3   = (const float*)d_in[22];
    const float* b3     = (const float*)d_in[23];
    const float* bn3_g  = (const float*)d_in[24];
    const float* bn3_b  = (const float*)d_in[25];
    const float* bn3_m  = (const float*)d_in[26];
    const float* bn3_v  = (const float*)d_in[27];
    const float* res2_w = (const float*)d_in[28];
    const float* res2_b = (const float*)d_in[29];
    float* out = (float*)d_out;

    float *cat1, *cat2, *cat3, *h1, *h2, *w1, *w2, *w3, *bi1, *bi2, *bi3;
    cudaGetSymbolAddress((void**)&cat1, g_cat1);
    cudaGetSymbolAddress((void**)&cat2, g_cat2);
    cudaGetSymbolAddress((void**)&cat3, g_cat3);
    cudaGetSymbolAddress((void**)&h1, g_h1);
    cudaGetSymbolAddress((void**)&h2, g_h2);
    cudaGetSymbolAddress((void**)&w1, g_w1);
    cudaGetSymbolAddress((void**)&w2, g_w2);
    cudaGetSymbolAddress((void**)&w3, g_w3);
    cudaGetSymbolAddress((void**)&bi1, g_bias1);
    cudaGetSymbolAddress((void**)&bi2, g_bias2);
    cudaGetSymbolAddress((void**)&bi3, g_bias3);

    // ---- CSR build + weight pack (launches 0..4) ----
    zero_deg<<<cdiv(NN, 256), 256>>>();
    hist_dst<<<cdiv(EE, 256), 256>>>(ei);
    scan_deg<<<1, 1024>>>();
    scatter_edges<<<cdiv(EE, 256), 256>>>(ei);
    pack_all<<<cdiv(FIN*NC1 + W1C*NC2 + W1C*NC3 + NC1 + NC2 + NC3, 256), 256>>>(
        w1_src, w1_dst, res0_w, res0_b, b1, w2_src, w2_dst,
        w3_src, w3_dst, res2_w, res2_b, b3);

    const int NB = cdiv(NN, 8);   // node kernel blocks (8 warps/block)

    // ===== layer 1 ===== (launch 5 = big GEMM, for ncu -s 5)
    sgemm_pack<128,128,16,8,8><<<dim3(cdiv(NC1,128), cdiv(NN,128)), 256>>>(
        x, w1, bi1, cat1, NN, FIN, NC1);
    gat_node4v<<<NB, 256>>>(cat1, NC1, 128, cat1 + 256, NC1, att1, nullptr,
                            bn1_g, bn1_b, bn1_m, bn1_v, h1, W1C, 1);

    // ===== layer 2 (identity residual) =====
    sgemm_pack<128,128,16,8,8><<<dim3(cdiv(NC2,128), cdiv(NN,128)), 256>>>(
        h1, w2, bi2, cat2, NN, W1C, NC2);
    gat_node4v<<<NB, 256>>>(cat2, NC2, 128, h1, W1C, att2, b2,
                            bn2_g, bn2_b, bn2_m, bn2_v, h2, W1C, 1);

    // ===== layer 3 (heads=1, 47 out) =====
    sgemm_pack<128,128,16,8,8><<<dim3(cdiv(NC3,128), cdiv(NN,128)), 256>>>(
        h2, w3, bi3, cat3, NN, W1C, NC3);
    gat_node1<<<NB, 256>>>(cat3, att3, bn3_g, bn3_b, bn3_m, bn3_v, out);
}

// round 5
// speedup vs baseline: 3.0742x; 1.2694x over previous
#include <cuda_runtime.h>
#include <cuda_bf16.h>
#include <cstdint>

// Problem constants
#define NN   50000
#define EE   800000
#define FIN  100
#define W1C  128
#define HEADS 4
#define HID  32
#define FOUT 47
#define NEG  0.2f
#define BNEPS 1e-5f

#define NC1 384               // layer-1 packed width: xl|xr|res
#define NC2 256               // layer-2 packed width: xl|xr
#define NC3 144               // layer-3 packed width: 48|48|48
#define GK  128               // padded K for all GEMMs

// ---------------- scratch (device globals) ----------------
__device__ float g_cat1[(size_t)NN * NC1];
__device__ float g_cat2[(size_t)NN * NC2];
__device__ float g_cat3[(size_t)NN * NC3];
__device__ float g_h1[(size_t)NN * W1C];
__device__ float g_h2[(size_t)NN * W1C];
__device__ __nv_bfloat16 g_xh[(size_t)NN * GK];
__device__ __nv_bfloat16 g_xl[(size_t)NN * GK];
__device__ __nv_bfloat16 g_h1h[(size_t)NN * GK];
__device__ __nv_bfloat16 g_h1l[(size_t)NN * GK];
__device__ __nv_bfloat16 g_h2h[(size_t)NN * GK];
__device__ __nv_bfloat16 g_h2l[(size_t)NN * GK];
__device__ __nv_bfloat16 g_w1h[(size_t)384 * GK];
__device__ __nv_bfloat16 g_w1l[(size_t)384 * GK];
__device__ __nv_bfloat16 g_w2h[(size_t)256 * GK];
__device__ __nv_bfloat16 g_w2l[(size_t)256 * GK];
__device__ __nv_bfloat16 g_w3h[(size_t)256 * GK];
__device__ __nv_bfloat16 g_w3l[(size_t)256 * GK];
__device__ float g_bias1[384];
__device__ float g_bias2[256];
__device__ float g_bias3[256];
__device__ int   g_deg[NN];
__device__ int   g_rowptr[NN + 1];
__device__ int   g_pos[NN];
__device__ int   g_adj[EE];

__device__ __forceinline__ uint32_t smem_u32(const void* p) {
    uint32_t a;
    asm("{ .reg .u64 t; cvta.to.shared.u64 t, %1; cvt.u32.u64 %0, t; }" : "=r"(a) : "l"(p));
    return a;
}

// ---------------- CSR build ----------------
__global__ void zero_deg() {
    int i = blockIdx.x * blockDim.x + threadIdx.x;
    if (i < NN) g_deg[i] = 0;
}
__global__ void hist_dst(const int* __restrict__ ei) {
    int i = blockIdx.x * blockDim.x + threadIdx.x;
    if (i < EE) atomicAdd(&g_deg[ei[EE + i]], 1);
}
__global__ void scan_deg() {
    __shared__ int ssum[1024];
    const int CH = 49;
    int t = threadIdx.x;
    int base = t * CH;
    int s = 0;
#pragma unroll 1
    for (int i = 0; i < CH; i++) { int idx = base + i; if (idx < NN) s += g_deg[idx]; }
    ssum[t] = s;
    __syncthreads();
    for (int off = 1; off < 1024; off <<= 1) {
        int v = (t >= off) ? ssum[t - off] : 0;
        __syncthreads();
        ssum[t] += v;
        __syncthreads();
    }
    int run = (t == 0) ? 0 : ssum[t - 1];
#pragma unroll 1
    for (int i = 0; i < CH; i++) {
        int idx = base + i;
        if (idx < NN) { g_rowptr[idx] = run; g_pos[idx] = run; run += g_deg[idx]; }
    }
    if (t == 0) g_rowptr[NN] = EE;
}
__global__ void scatter_edges(const int* __restrict__ ei) {
    int i = blockIdx.x * blockDim.x + threadIdx.x;
    if (i >= EE) return;
    int s = ei[i];
    int d = ei[EE + i];
    int p = atomicAdd(&g_pos[d], 1);
    g_adj[p] = s;
}

// ---------------- bf16 split helpers ----------------
__device__ __forceinline__ void split_bf(float v, __nv_bfloat16& h, __nv_bfloat16& l) {
    h = __float2bfloat16_rn(v);
    l = __float2bfloat16_rn(v - __bfloat162float(h));
}

__global__ void convert_x(const float* __restrict__ x) {
    int i = blockIdx.x * blockDim.x + threadIdx.x;
    if (i >= NN * 32) return;
    int row = i >> 5, c4 = (i & 31) * 4;
    __nv_bfloat16 h[4], l[4];
#pragma unroll
    for (int q = 0; q < 4; q++) {
        int k = c4 + q;
        float v = (k < FIN) ? x[(size_t)row * FIN + k] : 0.f;
        split_bf(v, h[q], l[q]);
    }
    *(uint2*)&g_xh[(size_t)row * GK + c4] = *(uint2*)h;
    *(uint2*)&g_xl[(size_t)row * GK + c4] = *(uint2*)l;
}

__global__ void pack_w(const float* __restrict__ w1s, const float* __restrict__ w1d,
                       const float* __restrict__ r0w, const float* __restrict__ r0b,
                       const float* __restrict__ b1,
                       const float* __restrict__ w2s, const float* __restrict__ w2d,
                       const float* __restrict__ w3s, const float* __restrict__ w3d,
                       const float* __restrict__ r2w, const float* __restrict__ r2b,
                       const float* __restrict__ b3)
{
    const int S1 = 384 * GK, S2 = 256 * GK, S3 = 256 * GK;
    int i = blockIdx.x * blockDim.x + threadIdx.x;
    if (i < S1) {
        int n = i / GK, k = i % GK;
        float v = 0.f;
        if (k < FIN) {
            if (n < 128)      v = w1s[k * 128 + n];
            else if (n < 256) v = w1d[k * 128 + (n - 128)];
            else              v = r0w[k * 128 + (n - 256)];
        }
        split_bf(v, g_w1h[i], g_w1l[i]);
        return;
    }
    i -= S1;
    if (i < S2) {
        int n = i / GK, k = i % GK;
        float v = (n < 128) ? w2s[k * 128 + n] : w2d[k * 128 + (n - 128)];
        split_bf(v, g_w2h[i], g_w2l[i]);
        return;
    }
    i -= S2;
    if (i < S3) {
        int n = i / GK, k = i % GK;
        float v = 0.f;
        if (n < 47)                  v = w3s[k * 47 + n];
        else if (n >= 48 && n < 95)  v = w3d[k * 47 + (n - 48)];
        else if (n >= 96 && n < 143) v = r2w[k * 47 + (n - 96)];
        split_bf(v, g_w3h[i], g_w3l[i]);
        return;
    }
    i -= S3;
    if (i < 384) { g_bias1[i] = (i >= 256) ? (r0b[i - 256] + b1[i - 256]) : 0.f; return; }
    i -= 384;
    if (i < 256) { g_bias2[i] = 0.f; return; }
    i -= 256;
    if (i < 256) { g_bias3[i] = (i >= 96 && i < 143) ? (r2b[i - 96] + b3[i - 96]) : 0.f; return; }
}

// ---------------- mma.sync GEMM: C[M, Ntot] = (Ah+Al) @ (Bh+Bl)^T + bias --------------
// A: [M, 128] bf16 hi/lo; B: [Nrows, 128] bf16 hi/lo, Nrows = gridDim.x*128 (pre-padded).
// CTA tile 128x128, full K=128 in SMEM, split into 3 products on tensor pipe.
// SMEM layout per tile: row-major [128][256B], 16B chunks swizzled: chunk' = chunk ^ (row&7).

#define SMT 32768
__device__ __forceinline__ uint32_t sw_off(int row, int chunk) {
    return (uint32_t)(row * 256 + ((chunk ^ (row & 7)) << 4));
}

__device__ __forceinline__ void ldsm_x4(uint32_t addr, uint32_t* r) {
    asm volatile("ldmatrix.sync.aligned.x4.m8n8.shared.b16 {%0,%1,%2,%3}, [%4];"
                 : "=r"(r[0]), "=r"(r[1]), "=r"(r[2]), "=r"(r[3]) : "r"(addr));
}
__device__ __forceinline__ void mma_bf16(float* c, const uint32_t* a, const uint32_t* b) {
    asm volatile("mma.sync.aligned.m16n8k16.row.col.f32.bf16.bf16.f32 "
                 "{%0,%1,%2,%3}, {%4,%5,%6,%7}, {%8,%9}, {%0,%1,%2,%3};"
                 : "+f"(c[0]), "+f"(c[1]), "+f"(c[2]), "+f"(c[3])
                 : "r"(a[0]), "r"(a[1]), "r"(a[2]), "r"(a[3]), "r"(b[0]), "r"(b[1]));
}

__global__ void __launch_bounds__(256)
gemm_mma(const __nv_bfloat16* __restrict__ Ah, const __nv_bfloat16* __restrict__ Al,
         const __nv_bfloat16* __restrict__ Bh, const __nv_bfloat16* __restrict__ Bl,
         const float* __restrict__ bias, float* __restrict__ C, int M, int Ntot, int ldc)
{
    extern __shared__ char smem[];
    char* sAh = smem;
    char* sAl = smem + SMT;
    char* sBh = smem + 2 * SMT;
    char* sBl = smem + 3 * SMT;

    const int tid = threadIdx.x;
    const int wid = tid >> 5, lane = tid & 31;
    const int brow = blockIdx.y * 128;
    const int bcol = blockIdx.x * 128;

    // ---- global -> smem (swizzled), 2048 chunks per tile ----
    for (int i = tid; i < 2048; i += 256) {
        int r = i >> 4, kc = i & 15;
        uint32_t so = sw_off(r, kc);
        int gr = brow + r;
        uint4 vh = {0, 0, 0, 0}, vl = {0, 0, 0, 0};
        if (gr < M) {
            vh = *(const uint4*)((const char*)(Ah + (size_t)gr * GK) + kc * 16);
            vl = *(const uint4*)((const char*)(Al + (size_t)gr * GK) + kc * 16);
        }
        *(uint4*)(sAh + so) = vh;
        *(uint4*)(sAl + so) = vl;
        int gn = bcol + r;                      // B pre-padded: no guard
        *(uint4*)(sBh + so) = *(const uint4*)((const char*)(Bh + (size_t)gn * GK) + kc * 16);
        *(uint4*)(sBl + so) = *(const uint4*)((const char*)(Bl + (size_t)gn * GK) + kc * 16);
    }
    __syncthreads();

    const uint32_t uAh = smem_u32(sAh), uAl = smem_u32(sAl);
    const uint32_t uBh = smem_u32(sBh), uBl = smem_u32(sBl);

    const int wm = (wid >> 2) * 64;             // 0 / 64
    const int wn = (wid & 3) * 32;              // 0,32,64,96

    float acc[4][4][4];
#pragma unroll
    for (int i = 0; i < 4; i++)
#pragma unroll
        for (int j = 0; j < 4; j++)
#pragma unroll
            for (int q = 0; q < 4; q++) acc[i][j][q] = 0.f;

    // ldmatrix lane->row/chunk maps
    const int a_r  = (lane & 15);               // + wm + ma*16
    const int a_kc = (lane >> 4);               // + ks*2
    const int b_r  = ((lane >> 4) & 1) * 8 + (lane & 7);   // mats 0/1: natom nb, 2/3: nb+1
    const int b_kc = ((lane >> 3) & 1);         // + ks*2

#pragma unroll
    for (int ks = 0; ks < 8; ks++) {
        uint32_t ah[4][4], al[4][4], bh[2][4], bl[2][4];
#pragma unroll
        for (int ma = 0; ma < 4; ma++) {
            int row = wm + ma * 16 + a_r;
            uint32_t off = sw_off(row, ks * 2 + a_kc);
            ldsm_x4(uAh + off, ah[ma]);
            ldsm_x4(uAl + off, al[ma]);
        }
#pragma unroll
        for (int nb = 0; nb < 2; nb++) {        // natom pairs (0,1),(2,3)
            int row = wn + nb * 16 + b_r;
            uint32_t off = sw_off(row, ks * 2 + b_kc);
            ldsm_x4(uBh + off, bh[nb]);
            ldsm_x4(uBl + off, bl[nb]);
        }
#pragma unroll
        for (int ma = 0; ma < 4; ma++)
#pragma unroll
            for (int na = 0; na < 4; na++) {
                const uint32_t* Bhf = &bh[na >> 1][(na & 1) * 2];
                const uint32_t* Blf = &bl[na >> 1][(na & 1) * 2];
                mma_bf16(acc[ma][na], ah[ma], Bhf);
                mma_bf16(acc[ma][na], al[ma], Bhf);
                mma_bf16(acc[ma][na], ah[ma], Blf);
            }
    }

    // ---- epilogue ----
    const int gq = lane >> 2, tg = lane & 3;
#pragma unroll
    for (int ma = 0; ma < 4; ma++) {
        int row0 = brow + wm + ma * 16 + gq;
        int row1 = row0 + 8;
#pragma unroll
        for (int na = 0; na < 4; na++) {
            int col = bcol + wn + na * 8 + tg * 2;
            if (col >= Ntot) continue;
            float b0 = bias[col], b1 = bias[col + 1];
            if (row0 < M) {
                float2 o = {acc[ma][na][0] + b0, acc[ma][na][1] + b1};
                *(float2*)(C + (size_t)row0 * ldc + col) = o;
            }
            if (row1 < M) {
                float2 o = {acc[ma][na][2] + b0, acc[ma][na][3] + b1};
                *(float2*)(C + (size_t)row1 * ldc + col) = o;
            }
        }
    }
}

// ---------------- fused node kernel: 4 heads x 32 ch, warp per node ----------------
__global__ void __launch_bounds__(256)
gat_node4v(const float* __restrict__ xlxr, int ldin, int xroff,
           const float* __restrict__ res, int ldres,
           const float* __restrict__ att, const float* __restrict__ bias,
           const float* __restrict__ bng, const float* __restrict__ bnb,
           const float* __restrict__ bnm, const float* __restrict__ bnv,
           float* __restrict__ outbuf, int ldout,
           __nv_bfloat16* __restrict__ outh, __nv_bfloat16* __restrict__ outl)
{
    int d    = (blockIdx.x * blockDim.x + threadIdx.x) >> 5;
    int lane = threadIdx.x & 31;
    if (d >= NN) return;
    int c = lane * 4;

    const float4 xr4 = *(const float4*)(xlxr + (size_t)d * ldin + xroff + c);
    const float4 at4 = *(const float4*)(att + c);

    int beg = g_rowptr[d], end = g_rowptr[d + 1];

    float m = -3.0e38f, den = 0.f;
    float4 acc = {0.f, 0.f, 0.f, 0.f};

    for (int j = beg - 1; j < end; j++) {           // j==beg-1 -> self loop
        int s = (j < beg) ? d : g_adj[j];
        float4 xv = *(const float4*)(xlxr + (size_t)s * ldin + c);
        float t0 = xv.x + xr4.x; t0 = (t0 > 0.f) ? t0 : NEG * t0;
        float t1 = xv.y + xr4.y; t1 = (t1 > 0.f) ? t1 : NEG * t1;
        float t2 = xv.z + xr4.z; t2 = (t2 > 0.f) ? t2 : NEG * t2;
        float t3 = xv.w + xr4.w; t3 = (t3 > 0.f) ? t3 : NEG * t3;
        float v = t0 * at4.x + t1 * at4.y + t2 * at4.z + t3 * at4.w;
        v += __shfl_xor_sync(0xffffffffu, v, 1);
        v += __shfl_xor_sync(0xffffffffu, v, 2);
        v += __shfl_xor_sync(0xffffffffu, v, 4);    // 8-lane group = one head
        float mn = fmaxf(m, v);
        float sc = __expf(m - mn);
        float w  = __expf(v - mn);
        den = den * sc + w;
        acc.x = acc.x * sc + w * xv.x;
        acc.y = acc.y * sc + w * xv.y;
        acc.z = acc.z * sc + w * xv.z;
        acc.w = acc.w * sc + w * xv.w;
        m = mn;
    }

    float inv = 1.f / den;
    float4 o;
    o.x = acc.x * inv; o.y = acc.y * inv; o.z = acc.z * inv; o.w = acc.w * inv;
    if (bias) {
        float4 bv = *(const float4*)(bias + c);
        o.x += bv.x; o.y += bv.y; o.z += bv.z; o.w += bv.w;
    }
    float4 rv = *(const float4*)(res + (size_t)d * ldres + c);
    o.x += rv.x; o.y += rv.y; o.z += rv.z; o.w += rv.w;

    float4 mm = *(const float4*)(bnm + c);
    float4 vv = *(const float4*)(bnv + c);
    float4 gg = *(const float4*)(bng + c);
    float4 bb = *(const float4*)(bnb + c);
    o.x = fmaxf((o.x - mm.x) * rsqrtf(vv.x + BNEPS) * gg.x + bb.x, 0.f);
    o.y = fmaxf((o.y - mm.y) * rsqrtf(vv.y + BNEPS) * gg.y + bb.y, 0.f);
    o.z = fmaxf((o.z - mm.z) * rsqrtf(vv.z + BNEPS) * gg.z + bb.z, 0.f);
    o.w = fmaxf((o.w - mm.w) * rsqrtf(vv.w + BNEPS) * gg.w + bb.w, 0.f);
    *(float4*)(outbuf + (size_t)d * ldout + c) = o;

    __nv_bfloat16 hh[4], ll[4];
    split_bf(o.x, hh[0], ll[0]);
    split_bf(o.y, hh[1], ll[1]);
    split_bf(o.z, hh[2], ll[2]);
    split_bf(o.w, hh[3], ll[3]);
    *(uint2*)&outh[(size_t)d * GK + c] = *(uint2*)hh;
    *(uint2*)&outl[(size_t)d * GK + c] = *(uint2*)ll;
}

// ---------------- fused node kernel: 1 head x 47 ch (warp per node) ----------------
__global__ void __launch_bounds__(256)
gat_node1(const float* __restrict__ cat, const float* __restrict__ att,
          const float* __restrict__ bng, const float* __restrict__ bnb,
          const float* __restrict__ bnm, const float* __restrict__ bnv,
          float* __restrict__ outbuf)
{
    int d    = (blockIdx.x * blockDim.x + threadIdx.x) >> 5;
    int lane = threadIdx.x & 31;
    if (d >= NN) return;

    int c0 = lane;
    int c1 = lane + 32;
    bool has1 = (c1 < FOUT);

    const float* rowd = cat + (size_t)d * NC3;
    float xr0 = rowd[48 + c0];
    float xr1 = has1 ? rowd[48 + c1] : 0.f;
    float a0  = att[c0];
    float a1  = has1 ? att[c1] : 0.f;

    int beg = g_rowptr[d], end = g_rowptr[d + 1];

    float m = -3.0e38f, den = 0.f, acc0 = 0.f, acc1 = 0.f;

    for (int j = beg - 1; j < end; j++) {
        int s = (j < beg) ? d : g_adj[j];
        const float* rows = cat + (size_t)s * NC3;
        float x0 = rows[c0];
        float x1 = has1 ? rows[c1] : 0.f;
        float t0 = x0 + xr0; t0 = (t0 > 0.f) ? t0 : NEG * t0;
        float t1 = x1 + xr1; t1 = (t1 > 0.f) ? t1 : NEG * t1;
        float v = t0 * a0 + t1 * a1;
#pragma unroll
        for (int o = 16; o; o >>= 1) v += __shfl_xor_sync(0xffffffffu, v, o);
        float mn = fmaxf(m, v);
        float sc = __expf(m - mn);
        float w  = __expf(v - mn);
        den  = den  * sc + w;
        acc0 = acc0 * sc + w * x0;
        acc1 = acc1 * sc + w * x1;
        m = mn;
    }

    float inv = 1.f / den;
    {
        float val = acc0 * inv + rowd[96 + c0];
        val = (val - bnm[c0]) * rsqrtf(bnv[c0] + BNEPS) * bng[c0] + bnb[c0];
        outbuf[(size_t)d * FOUT + c0] = val;
    }
    if (has1) {
        float val = acc1 * inv + rowd[96 + c1];
        val = (val - bnm[c1]) * rsqrtf(bnv[c1] + BNEPS) * bng[c1] + bnb[c1];
        outbuf[(size_t)d * FOUT + c1] = val;
    }
}

// ---------------- launch ----------------
static inline int cdiv(int a, int b) { return (a + b - 1) / b; }

extern "C" void kernel_launch(void* const* d_in, const int* in_sizes, int n_in,
                              void* d_out, int out_size)
{
    const float* x      = (const float*)d_in[0];
    const int*   ei     = (const int*)  d_in[1];
    const float* w1_src = (const float*)d_in[2];
    const float* w1_dst = (const float*)d_in[3];
    const float* att1   = (const float*)d_in[4];
    const float* b1     = (const float*)d_in[5];
    const float* bn1_g  = (const float*)d_in[6];
    const float* bn1_b  = (const float*)d_in[7];
    const float* bn1_m  = (const float*)d_in[8];
    const float* bn1_v  = (const float*)d_in[9];
    const float* res0_w = (const float*)d_in[10];
    const float* res0_b = (const float*)d_in[11];
    const float* w2_src = (const float*)d_in[12];
    const float* w2_dst = (const float*)d_in[13];
    const float* att2   = (const float*)d_in[14];
    const float* b2     = (const float*)d_in[15];
    const float* bn2_g  = (const float*)d_in[16];
    const float* bn2_b  = (const float*)d_in[17];
    const float* bn2_m  = (const float*)d_in[18];
    const float* bn2_v  = (const float*)d_in[19];
    const float* w3_src = (const float*)d_in[20];
    const float* w3_dst = (const float*)d_in[21];
    const float* att3   = (const float*)d_in[22];
    const float* b3     = (const float*)d_in[23];
    const float* bn3_g  = (const float*)d_in[24];
    const float* bn3_b  = (const float*)d_in[25];
    const float* bn3_m  = (const float*)d_in[26];
    const float* bn3_v  = (const float*)d_in[27];
    const float* res2_w = (const float*)d_in[28];
    const float* res2_b = (const float*)d_in[29];
    float* out = (float*)d_out;

    float *cat1, *cat2, *cat3, *h1, *h2, *bi1, *bi2, *bi3;
    __nv_bfloat16 *xh, *xl, *h1h, *h1l, *h2h, *h2l, *w1h, *w1l, *w2h, *w2l, *w3h, *w3l;
    cudaGetSymbolAddress((void**)&cat1, g_cat1);
    cudaGetSymbolAddress((void**)&cat2, g_cat2);
    cudaGetSymbolAddress((void**)&cat3, g_cat3);
    cudaGetSymbolAddress((void**)&h1, g_h1);
    cudaGetSymbolAddress((void**)&h2, g_h2);
    cudaGetSymbolAddress((void**)&xh, g_xh);
    cudaGetSymbolAddress((void**)&xl, g_xl);
    cudaGetSymbolAddress((void**)&h1h, g_h1h);
    cudaGetSymbolAddress((void**)&h1l, g_h1l);
    cudaGetSymbolAddress((void**)&h2h, g_h2h);
    cudaGetSymbolAddress((void**)&h2l, g_h2l);
    cudaGetSymbolAddress((void**)&w1h, g_w1h);
    cudaGetSymbolAddress((void**)&w1l, g_w1l);
    cudaGetSymbolAddress((void**)&w2h, g_w2h);
    cudaGetSymbolAddress((void**)&w2l, g_w2l);
    cudaGetSymbolAddress((void**)&w3h, g_w3h);
    cudaGetSymbolAddress((void**)&w3l, g_w3l);
    cudaGetSymbolAddress((void**)&bi1, g_bias1);
    cudaGetSymbolAddress((void**)&bi2, g_bias2);
    cudaGetSymbolAddress((void**)&bi3, g_bias3);

    cudaFuncSetAttribute(gemm_mma, cudaFuncAttributeMaxDynamicSharedMemorySize, 4 * SMT);

    // ---- prep: CSR + conversions + weight pack ----
    zero_deg<<<cdiv(NN, 256), 256>>>();
    hist_dst<<<cdiv(EE, 256), 256>>>(ei);
    scan_deg<<<1, 1024>>>();
    scatter_edges<<<cdiv(EE, 256), 256>>>(ei);
    convert_x<<<cdiv(NN * 32, 256), 256>>>(x);
    pack_w<<<cdiv((384 + 256 + 256) * GK + 384 + 256 + 256, 256), 256>>>(
        w1_src, w1_dst, res0_w, res0_b, b1, w2_src, w2_dst,
        w3_src, w3_dst, res2_w, res2_b, b3);

    const int MT = cdiv(NN, 128);     // 391 M-tiles
    const int NB = cdiv(NN, 8);

    // ===== layer 1 =====
    gemm_mma<<<dim3(3, MT), 256, 4 * SMT>>>(xh, xl, w1h, w1l, bi1, cat1, NN, NC1, NC1);
    gat_node4v<<<NB, 256>>>(cat1, NC1, 128, cat1 + 256, NC1, att1, nullptr,
                            bn1_g, bn1_b, bn1_m, bn1_v, h1, W1C, h1h, h1l);

    // ===== layer 2 (identity residual) =====
    gemm_mma<<<dim3(2, MT), 256, 4 * SMT>>>(h1h, h1l, w2h, w2l, bi2, cat2, NN, NC2, NC2);
    gat_node4v<<<NB, 256>>>(cat2, NC2, 128, h1, W1C, att2, b2,
                            bn2_g, bn2_b, bn2_m, bn2_v, h2, W1C, h2h, h2l);

    // ===== layer 3 (heads=1, 47 out) =====
    gemm_mma<<<dim3(2, MT), 256, 4 * SMT>>>(h2h, h2l, w3h, w3l, bi3, cat3, NN, NC3, NC3);
    gat_node1<<<NB, 256>>>(cat3, att3, bn3_g, bn3_b, bn3_m, bn3_v, out);
}

// round 6
// speedup vs baseline: 3.6520x; 1.1880x over previous
#include <cuda_runtime.h>
#include <cuda_bf16.h>
#include <cstdint>

// Problem constants
#define NN   50000
#define EE   800000
#define FIN  100
#define W1C  128
#define HEADS 4
#define HID  32
#define FOUT 47
#define NEG  0.2f
#define BNEPS 1e-5f

#define NC1 384               // layer-1 packed width: xl|xr|res
#define NC2 256               // layer-2 packed width: xl|xr
#define NC3 144               // layer-3 packed width: 48|48|48
#define GK  128               // padded K for all GEMMs

// ---------------- scratch (device globals) ----------------
__device__ float g_cat1[(size_t)NN * NC1];
__device__ float g_cat2[(size_t)NN * NC2];
__device__ float g_cat3[(size_t)NN * NC3];
__device__ float g_h1[(size_t)NN * W1C];
__device__ float g_h2[(size_t)NN * W1C];
__device__ __nv_bfloat16 g_xh[(size_t)NN * GK];
__device__ __nv_bfloat16 g_xl[(size_t)NN * GK];
__device__ __nv_bfloat16 g_h1h[(size_t)NN * GK];
__device__ __nv_bfloat16 g_h1l[(size_t)NN * GK];
__device__ __nv_bfloat16 g_h2h[(size_t)NN * GK];
__device__ __nv_bfloat16 g_h2l[(size_t)NN * GK];
__device__ __nv_bfloat16 g_w1h[(size_t)384 * GK];
__device__ __nv_bfloat16 g_w1l[(size_t)384 * GK];
__device__ __nv_bfloat16 g_w2h[(size_t)256 * GK];
__device__ __nv_bfloat16 g_w2l[(size_t)256 * GK];
__device__ __nv_bfloat16 g_w3h[(size_t)256 * GK];
__device__ __nv_bfloat16 g_w3l[(size_t)256 * GK];
__device__ float g_bias1[384];
__device__ float g_bias2[256];
__device__ float g_bias3[256];
__device__ int   g_deg[NN];
__device__ int   g_rowptr[NN + 1];
__device__ int   g_pos[NN];
__device__ int   g_adj[EE];

__device__ __forceinline__ uint32_t smem_u32(const void* p) {
    uint32_t a;
    asm("{ .reg .u64 t; cvta.to.shared.u64 t, %1; cvt.u32.u64 %0, t; }" : "=r"(a) : "l"(p));
    return a;
}
__device__ __forceinline__ void cp16(uint32_t dst, const void* src, bool valid) {
    asm volatile("cp.async.cg.shared.global [%0], [%1], 16, %2;"
                 :: "r"(dst), "l"(src), "r"(valid ? 16 : 0));
}

// ---------------- CSR build ----------------
__global__ void zero_deg() {
    int i = blockIdx.x * blockDim.x + threadIdx.x;
    if (i < NN) g_deg[i] = 0;
}
__global__ void hist_dst(const int* __restrict__ ei) {
    int i = blockIdx.x * blockDim.x + threadIdx.x;
    if (i < EE) atomicAdd(&g_deg[ei[EE + i]], 1);
}
__global__ void scan_deg() {
    __shared__ int ssum[1024];
    const int CH = 49;
    int t = threadIdx.x;
    int base = t * CH;
    int s = 0;
#pragma unroll 1
    for (int i = 0; i < CH; i++) { int idx = base + i; if (idx < NN) s += g_deg[idx]; }
    ssum[t] = s;
    __syncthreads();
    for (int off = 1; off < 1024; off <<= 1) {
        int v = (t >= off) ? ssum[t - off] : 0;
        __syncthreads();
        ssum[t] += v;
        __syncthreads();
    }
    int run = (t == 0) ? 0 : ssum[t - 1];
#pragma unroll 1
    for (int i = 0; i < CH; i++) {
        int idx = base + i;
        if (idx < NN) { g_rowptr[idx] = run; g_pos[idx] = run; run += g_deg[idx]; }
    }
    if (t == 0) g_rowptr[NN] = EE;
}
__global__ void scatter_edges(const int* __restrict__ ei) {
    int i = blockIdx.x * blockDim.x + threadIdx.x;
    if (i >= EE) return;
    int s = ei[i];
    int d = ei[EE + i];
    int p = atomicAdd(&g_pos[d], 1);
    g_adj[p] = s;
}

// ---------------- bf16 split helpers ----------------
__device__ __forceinline__ void split_bf(float v, __nv_bfloat16& h, __nv_bfloat16& l) {
    h = __float2bfloat16_rn(v);
    l = __float2bfloat16_rn(v - __bfloat162float(h));
}

__global__ void convert_x(const float* __restrict__ x) {
    int i = blockIdx.x * blockDim.x + threadIdx.x;
    if (i >= NN * 32) return;
    int row = i >> 5, c4 = (i & 31) * 4;
    __nv_bfloat16 h[4], l[4];
#pragma unroll
    for (int q = 0; q < 4; q++) {
        int k = c4 + q;
        float v = (k < FIN) ? x[(size_t)row * FIN + k] : 0.f;
        split_bf(v, h[q], l[q]);
    }
    *(uint2*)&g_xh[(size_t)row * GK + c4] = *(uint2*)h;
    *(uint2*)&g_xl[(size_t)row * GK + c4] = *(uint2*)l;
}

__global__ void pack_w(const float* __restrict__ w1s, const float* __restrict__ w1d,
                       const float* __restrict__ r0w, const float* __restrict__ r0b,
                       const float* __restrict__ b1,
                       const float* __restrict__ w2s, const float* __restrict__ w2d,
                       const float* __restrict__ w3s, const float* __restrict__ w3d,
                       const float* __restrict__ r2w, const float* __restrict__ r2b,
                       const float* __restrict__ b3)
{
    const int S1 = 384 * GK, S2 = 256 * GK, S3 = 256 * GK;
    int i = blockIdx.x * blockDim.x + threadIdx.x;
    if (i < S1) {
        int n = i / GK, k = i % GK;
        float v = 0.f;
        if (k < FIN) {
            if (n < 128)      v = w1s[k * 128 + n];
            else if (n < 256) v = w1d[k * 128 + (n - 128)];
            else              v = r0w[k * 128 + (n - 256)];
        }
        split_bf(v, g_w1h[i], g_w1l[i]);
        return;
    }
    i -= S1;
    if (i < S2) {
        int n = i / GK, k = i % GK;
        float v = (n < 128) ? w2s[k * 128 + n] : w2d[k * 128 + (n - 128)];
        split_bf(v, g_w2h[i], g_w2l[i]);
        return;
    }
    i -= S2;
    if (i < S3) {
        int n = i / GK, k = i % GK;
        float v = 0.f;
        if (n < 47)                  v = w3s[k * 47 + n];
        else if (n >= 48 && n < 95)  v = w3d[k * 47 + (n - 48)];
        else if (n >= 96 && n < 143) v = r2w[k * 47 + (n - 96)];
        split_bf(v, g_w3h[i], g_w3l[i]);
        return;
    }
    i -= S3;
    if (i < 384) { g_bias1[i] = (i >= 256) ? (r0b[i - 256] + b1[i - 256]) : 0.f; return; }
    i -= 384;
    if (i < 256) { g_bias2[i] = 0.f; return; }
    i -= 256;
    if (i < 256) { g_bias3[i] = (i >= 96 && i < 143) ? (r2b[i - 96] + b3[i - 96]) : 0.f; return; }
}

// ---------------- mma.sync GEMM: C[M, Ntot] = (Ah+Al) @ (Bh+Bl)^T + bias --------------
// CTA tile 64x128, full K=128 in SMEM (96 KB -> 2 CTAs/SM), cp.async loads.
// SMEM per tile: row-major [rows][256B], 16B chunks swizzled: chunk' = chunk ^ (row&7).

#define OFF_AH 0
#define OFF_AL 16384
#define OFF_BH 32768
#define OFF_BL 65536
#define SM_GEMM 98304

__device__ __forceinline__ uint32_t sw_off(int row, int chunk) {
    return (uint32_t)(row * 256 + ((chunk ^ (row & 7)) << 4));
}
__device__ __forceinline__ void ldsm_x4(uint32_t addr, uint32_t* r) {
    asm volatile("ldmatrix.sync.aligned.x4.m8n8.shared.b16 {%0,%1,%2,%3}, [%4];"
                 : "=r"(r[0]), "=r"(r[1]), "=r"(r[2]), "=r"(r[3]) : "r"(addr));
}
__device__ __forceinline__ void mma_bf16(float* c, const uint32_t* a, const uint32_t* b) {
    asm volatile("mma.sync.aligned.m16n8k16.row.col.f32.bf16.bf16.f32 "
                 "{%0,%1,%2,%3}, {%4,%5,%6,%7}, {%8,%9}, {%0,%1,%2,%3};"
                 : "+f"(c[0]), "+f"(c[1]), "+f"(c[2]), "+f"(c[3])
                 : "r"(a[0]), "r"(a[1]), "r"(a[2]), "r"(a[3]), "r"(b[0]), "r"(b[1]));
}

__global__ void __launch_bounds__(256, 2)
gemm_mma(const __nv_bfloat16* __restrict__ Ah, const __nv_bfloat16* __restrict__ Al,
         const __nv_bfloat16* __restrict__ Bh, const __nv_bfloat16* __restrict__ Bl,
         const float* __restrict__ bias, float* __restrict__ C, int M, int Ntot, int ldc)
{
    extern __shared__ char smem[];
    const uint32_t sb = smem_u32(smem);

    const int tid = threadIdx.x;
    const int wid = tid >> 5, lane = tid & 31;
    const int brow = blockIdx.y * 64;
    const int bcol = blockIdx.x * 128;

    // ---- async loads: A (64 rows) hi/lo, B (128 rows) hi/lo ----
    for (int i = tid; i < 1024; i += 256) {
        int r = i >> 4, kc = i & 15;
        uint32_t so = sw_off(r, kc);
        int gr = brow + r;
        bool v = gr < M;
        const char* pa = (const char*)(Ah + (size_t)gr * GK) + kc * 16;
        const char* pl = (const char*)(Al + (size_t)gr * GK) + kc * 16;
        cp16(sb + OFF_AH + so, v ? pa : (const char*)Ah, v);
        cp16(sb + OFF_AL + so, v ? pl : (const char*)Al, v);
    }
    for (int i = tid; i < 2048; i += 256) {
        int r = i >> 4, kc = i & 15;
        uint32_t so = sw_off(r, kc);
        int gn = bcol + r;                      // B pre-padded: no guard
        cp16(sb + OFF_BH + so, (const char*)(Bh + (size_t)gn * GK) + kc * 16, true);
        cp16(sb + OFF_BL + so, (const char*)(Bl + (size_t)gn * GK) + kc * 16, true);
    }
    asm volatile("cp.async.commit_group;" ::: "memory");
    asm volatile("cp.async.wait_group 0;" ::: "memory");
    __syncthreads();

    const int wm = (wid >> 2) * 32;             // 0 / 32
    const int wn = (wid & 3) * 32;              // 0,32,64,96

    float acc[2][4][4];
#pragma unroll
    for (int i = 0; i < 2; i++)
#pragma unroll
        for (int j = 0; j < 4; j++)
#pragma unroll
            for (int q = 0; q < 4; q++) acc[i][j][q] = 0.f;

    const int a_r  = (lane & 15);
    const int a_kc = (lane >> 4);
    const int b_r  = ((lane >> 4) & 1) * 8 + (lane & 7);
    const int b_kc = ((lane >> 3) & 1);

#pragma unroll
    for (int ks = 0; ks < 8; ks++) {
        uint32_t ah[2][4], al[2][4], bh[2][4], bl[2][4];
#pragma unroll
        for (int ma = 0; ma < 2; ma++) {
            int row = wm + ma * 16 + a_r;
            uint32_t off = sw_off(row, ks * 2 + a_kc);
            ldsm_x4(sb + OFF_AH + off, ah[ma]);
            ldsm_x4(sb + OFF_AL + off, al[ma]);
        }
#pragma unroll
        for (int nb = 0; nb < 2; nb++) {
            int row = wn + nb * 16 + b_r;
            uint32_t off = sw_off(row, ks * 2 + b_kc);
            ldsm_x4(sb + OFF_BH + off, bh[nb]);
            ldsm_x4(sb + OFF_BL + off, bl[nb]);
        }
#pragma unroll
        for (int ma = 0; ma < 2; ma++)
#pragma unroll
            for (int na = 0; na < 4; na++) {
                const uint32_t* Bhf = &bh[na >> 1][(na & 1) * 2];
                const uint32_t* Blf = &bl[na >> 1][(na & 1) * 2];
                mma_bf16(acc[ma][na], ah[ma], Bhf);
                mma_bf16(acc[ma][na], al[ma], Bhf);
                mma_bf16(acc[ma][na], ah[ma], Blf);
            }
    }

    // ---- epilogue ----
    const int gq = lane >> 2, tg = lane & 3;
#pragma unroll
    for (int ma = 0; ma < 2; ma++) {
        int row0 = brow + wm + ma * 16 + gq;
        int row1 = row0 + 8;
#pragma unroll
        for (int na = 0; na < 4; na++) {
            int col = bcol + wn + na * 8 + tg * 2;
            if (col >= Ntot) continue;
            float b0 = bias[col], b1 = bias[col + 1];
            if (row0 < M) {
                float2 o = {acc[ma][na][0] + b0, acc[ma][na][1] + b1};
                *(float2*)(C + (size_t)row0 * ldc + col) = o;
            }
            if (row1 < M) {
                float2 o = {acc[ma][na][2] + b0, acc[ma][na][3] + b1};
                *(float2*)(C + (size_t)row1 * ldc + col) = o;
            }
        }
    }
}

// ---------------- fused node kernel: 4 heads x 32 ch, warp per node ----------------
__global__ void __launch_bounds__(256)
gat_node4v(const float* __restrict__ xlxr, int ldin, int xroff,
           const float* __restrict__ res, int ldres,
           const float* __restrict__ att, const float* __restrict__ bias,
           const float* __restrict__ bng, const float* __restrict__ bnb,
           const float* __restrict__ bnm, const float* __restrict__ bnv,
           float* __restrict__ outbuf, int ldout,
           __nv_bfloat16* __restrict__ outh, __nv_bfloat16* __restrict__ outl)
{
    int d    = (blockIdx.x * blockDim.x + threadIdx.x) >> 5;
    int lane = threadIdx.x & 31;
    if (d >= NN) return;
    int c = lane * 4;

    const float4 xr4 = *(const float4*)(xlxr + (size_t)d * ldin + xroff + c);
    const float4 at4 = *(const float4*)(att + c);

    int beg = g_rowptr[d], end = g_rowptr[d + 1];

    float m = -3.0e38f, den = 0.f;
    float4 acc = {0.f, 0.f, 0.f, 0.f};

    for (int j = beg - 1; j < end; j++) {           // j==beg-1 -> self loop
        int s = (j < beg) ? d : g_adj[j];
        float4 xv = *(const float4*)(xlxr + (size_t)s * ldin + c);
        float t0 = xv.x + xr4.x; t0 = (t0 > 0.f) ? t0 : NEG * t0;
        float t1 = xv.y + xr4.y; t1 = (t1 > 0.f) ? t1 : NEG * t1;
        float t2 = xv.z + xr4.z; t2 = (t2 > 0.f) ? t2 : NEG * t2;
        float t3 = xv.w + xr4.w; t3 = (t3 > 0.f) ? t3 : NEG * t3;
        float v = t0 * at4.x + t1 * at4.y + t2 * at4.z + t3 * at4.w;
        v += __shfl_xor_sync(0xffffffffu, v, 1);
        v += __shfl_xor_sync(0xffffffffu, v, 2);
        v += __shfl_xor_sync(0xffffffffu, v, 4);    // 8-lane group = one head
        float mn = fmaxf(m, v);
        float sc = __expf(m - mn);
        float w  = __expf(v - mn);
        den = den * sc + w;
        acc.x = acc.x * sc + w * xv.x;
        acc.y = acc.y * sc + w * xv.y;
        acc.z = acc.z * sc + w * xv.z;
        acc.w = acc.w * sc + w * xv.w;
        m = mn;
    }

    float inv = 1.f / den;
    float4 o;
    o.x = acc.x * inv; o.y = acc.y * inv; o.z = acc.z * inv; o.w = acc.w * inv;
    if (bias) {
        float4 bv = *(const float4*)(bias + c);
        o.x += bv.x; o.y += bv.y; o.z += bv.z; o.w += bv.w;
    }
    float4 rv = *(const float4*)(res + (size_t)d * ldres + c);
    o.x += rv.x; o.y += rv.y; o.z += rv.z; o.w += rv.w;

    float4 mm = *(const float4*)(bnm + c);
    float4 vv = *(const float4*)(bnv + c);
    float4 gg = *(const float4*)(bng + c);
    float4 bb = *(const float4*)(bnb + c);
    o.x = fmaxf((o.x - mm.x) * rsqrtf(vv.x + BNEPS) * gg.x + bb.x, 0.f);
    o.y = fmaxf((o.y - mm.y) * rsqrtf(vv.y + BNEPS) * gg.y + bb.y, 0.f);
    o.z = fmaxf((o.z - mm.z) * rsqrtf(vv.z + BNEPS) * gg.z + bb.z, 0.f);
    o.w = fmaxf((o.w - mm.w) * rsqrtf(vv.w + BNEPS) * gg.w + bb.w, 0.f);
    *(float4*)(outbuf + (size_t)d * ldout + c) = o;

    __nv_bfloat16 hh[4], ll[4];
    split_bf(o.x, hh[0], ll[0]);
    split_bf(o.y, hh[1], ll[1]);
    split_bf(o.z, hh[2], ll[2]);
    split_bf(o.w, hh[3], ll[3]);
    *(uint2*)&outh[(size_t)d * GK + c] = *(uint2*)hh;
    *(uint2*)&outl[(size_t)d * GK + c] = *(uint2*)ll;
}

// ---------------- fused node kernel: 1 head x 47 ch (warp per node) ----------------
__global__ void __launch_bounds__(256)
gat_node1(const float* __restrict__ cat, const float* __restrict__ att,
          const float* __restrict__ bng, const float* __restrict__ bnb,
          const float* __restrict__ bnm, const float* __restrict__ bnv,
          float* __restrict__ outbuf)
{
    int d    = (blockIdx.x * blockDim.x + threadIdx.x) >> 5;
    int lane = threadIdx.x & 31;
    if (d >= NN) return;

    int c0 = lane;
    int c1 = lane + 32;
    bool has1 = (c1 < FOUT);

    const float* rowd = cat + (size_t)d * NC3;
    float xr0 = rowd[48 + c0];
    float xr1 = has1 ? rowd[48 + c1] : 0.f;
    float a0  = att[c0];
    float a1  = has1 ? att[c1] : 0.f;

    int beg = g_rowptr[d], end = g_rowptr[d + 1];

    float m = -3.0e38f, den = 0.f, acc0 = 0.f, acc1 = 0.f;

    for (int j = beg - 1; j < end; j++) {
        int s = (j < beg) ? d : g_adj[j];
        const float* rows = cat + (size_t)s * NC3;
        float x0 = rows[c0];
        float x1 = has1 ? rows[c1] : 0.f;
        float t0 = x0 + xr0; t0 = (t0 > 0.f) ? t0 : NEG * t0;
        float t1 = x1 + xr1; t1 = (t1 > 0.f) ? t1 : NEG * t1;
        float v = t0 * a0 + t1 * a1;
#pragma unroll
        for (int o = 16; o; o >>= 1) v += __shfl_xor_sync(0xffffffffu, v, o);
        float mn = fmaxf(m, v);
        float sc = __expf(m - mn);
        float w  = __expf(v - mn);
        den  = den  * sc + w;
        acc0 = acc0 * sc + w * x0;
        acc1 = acc1 * sc + w * x1;
        m = mn;
    }

    float inv = 1.f / den;
    {
        float val = acc0 * inv + rowd[96 + c0];
        val = (val - bnm[c0]) * rsqrtf(bnv[c0] + BNEPS) * bng[c0] + bnb[c0];
        outbuf[(size_t)d * FOUT + c0] = val;
    }
    if (has1) {
        float val = acc1 * inv + rowd[96 + c1];
        val = (val - bnm[c1]) * rsqrtf(bnv[c1] + BNEPS) * bng[c1] + bnb[c1];
        outbuf[(size_t)d * FOUT + c1] = val;
    }
}

// ---------------- launch ----------------
static inline int cdiv(int a, int b) { return (a + b - 1) / b; }

extern "C" void kernel_launch(void* const* d_in, const int* in_sizes, int n_in,
                              void* d_out, int out_size)
{
    const float* x      = (const float*)d_in[0];
    const int*   ei     = (const int*)  d_in[1];
    const float* w1_src = (const float*)d_in[2];
    const float* w1_dst = (const float*)d_in[3];
    const float* att1   = (const float*)d_in[4];
    const float* b1     = (const float*)d_in[5];
    const float* bn1_g  = (const float*)d_in[6];
    const float* bn1_b  = (const float*)d_in[7];
    const float* bn1_m  = (const float*)d_in[8];
    const float* bn1_v  = (const float*)d_in[9];
    const float* res0_w = (const float*)d_in[10];
    const float* res0_b = (const float*)d_in[11];
    const float* w2_src = (const float*)d_in[12];
    const float* w2_dst = (const float*)d_in[13];
    const float* att2   = (const float*)d_in[14];
    const float* b2     = (const float*)d_in[15];
    const float* bn2_g  = (const float*)d_in[16];
    const float* bn2_b  = (const float*)d_in[17];
    const float* bn2_m  = (const float*)d_in[18];
    const float* bn2_v  = (const float*)d_in[19];
    const float* w3_src = (const float*)d_in[20];
    const float* w3_dst = (const float*)d_in[21];
    const float* att3   = (const float*)d_in[22];
    const float* b3     = (const float*)d_in[23];
    const float* bn3_g  = (const float*)d_in[24];
    const float* bn3_b  = (const float*)d_in[25];
    const float* bn3_m  = (const float*)d_in[26];
    const float* bn3_v  = (const float*)d_in[27];
    const float* res2_w = (const float*)d_in[28];
    const float* res2_b = (const float*)d_in[29];
    float* out = (float*)d_out;

    float *cat1, *cat2, *cat3, *h1, *h2, *bi1, *bi2, *bi3;
    __nv_bfloat16 *xh, *xl, *h1h, *h1l, *h2h, *h2l, *w1h, *w1l, *w2h, *w2l, *w3h, *w3l;
    cudaGetSymbolAddress((void**)&cat1, g_cat1);
    cudaGetSymbolAddress((void**)&cat2, g_cat2);
    cudaGetSymbolAddress((void**)&cat3, g_cat3);
    cudaGetSymbolAddress((void**)&h1, g_h1);
    cudaGetSymbolAddress((void**)&h2, g_h2);
    cudaGetSymbolAddress((void**)&xh, g_xh);
    cudaGetSymbolAddress((void**)&xl, g_xl);
    cudaGetSymbolAddress((void**)&h1h, g_h1h);
    cudaGetSymbolAddress((void**)&h1l, g_h1l);
    cudaGetSymbolAddress((void**)&h2h, g_h2h);
    cudaGetSymbolAddress((void**)&h2l, g_h2l);
    cudaGetSymbolAddress((void**)&w1h, g_w1h);
    cudaGetSymbolAddress((void**)&w1l, g_w1l);
    cudaGetSymbolAddress((void**)&w2h, g_w2h);
    cudaGetSymbolAddress((void**)&w2l, g_w2l);
    cudaGetSymbolAddress((void**)&w3h, g_w3h);
    cudaGetSymbolAddress((void**)&w3l, g_w3l);
    cudaGetSymbolAddress((void**)&bi1, g_bias1);
    cudaGetSymbolAddress((void**)&bi2, g_bias2);
    cudaGetSymbolAddress((void**)&bi3, g_bias3);

    cudaFuncSetAttribute(gemm_mma, cudaFuncAttributeMaxDynamicSharedMemorySize, SM_GEMM);

    const int MT = cdiv(NN, 64);      // 782 M-tiles
    const int NB = cdiv(NN, 8);

    // launch order: gemm L1 at index 3 (ncu capture slot)
    convert_x<<<cdiv(NN * 32, 256), 256>>>(x);                                  // 0
    pack_w<<<cdiv((384 + 256 + 256) * GK + 384 + 256 + 256, 256), 256>>>(       // 1
        w1_src, w1_dst, res0_w, res0_b, b1, w2_src, w2_dst,
        w3_src, w3_dst, res2_w, res2_b, b3);
    zero_deg<<<cdiv(NN, 256), 256>>>();                                         // 2
    gemm_mma<<<dim3(3, MT), 256, SM_GEMM>>>(xh, xl, w1h, w1l, bi1, cat1, NN, NC1, NC1);  // 3
    hist_dst<<<cdiv(EE, 256), 256>>>(ei);                                       // 4
    scan_deg<<<1, 1024>>>();                                                    // 5
    scatter_edges<<<cdiv(EE, 256), 256>>>(ei);                                  // 6

    // ===== layer 1 node phase =====
    gat_node4v<<<NB, 256>>>(cat1, NC1, 128, cat1 + 256, NC1, att1, nullptr,
                            bn1_g, bn1_b, bn1_m, bn1_v, h1, W1C, h1h, h1l);

    // ===== layer 2 (identity residual) =====
    gemm_mma<<<dim3(2, MT), 256, SM_GEMM>>>(h1h, h1l, w2h, w2l, bi2, cat2, NN, NC2, NC2);
    gat_node4v<<<NB, 256>>>(cat2, NC2, 128, h1, W1C, att2, b2,
                            bn2_g, bn2_b, bn2_m, bn2_v, h2, W1C, h2h, h2l);

    // ===== layer 3 (heads=1, 47 out) =====
    gemm_mma<<<dim3(2, MT), 256, SM_GEMM>>>(h2h, h2l, w3h, w3l, bi3, cat3, NN, NC3, NC3);
    gat_node1<<<NB, 256>>>(cat3, att3, bn3_g, bn3_b, bn3_m, bn3_v, out);
}

// round 7
// speedup vs baseline: 3.8748x; 1.0610x over previous
#include <cuda_runtime.h>
#include <cuda_bf16.h>
#include <cstdint>

// Problem constants
#define NN   50000
#define EE   800000
#define FIN  100
#define W1C  128
#define HEADS 4
#define HID  32
#define FOUT 47
#define NEG  0.2f
#define BNEPS 1e-5f

#define NC1 384               // layer-1 packed width: xl|xr|res
#define NC2 256               // layer-2 packed width: xl|xr
#define NC3 144               // layer-3 packed width: 48|48|48
#define GK  128               // padded K for all GEMMs

// ---------------- scratch (device globals) ----------------
__device__ float g_cat1[(size_t)NN * NC1];
__device__ float g_cat2[(size_t)NN * NC2];
__device__ float g_cat3[(size_t)NN * NC3];
__device__ float g_h1[(size_t)NN * W1C];
__device__ float g_h2[(size_t)NN * W1C];
__device__ __nv_bfloat16 g_xh[(size_t)NN * GK];
__device__ __nv_bfloat16 g_xl[(size_t)NN * GK];
__device__ __nv_bfloat16 g_h1h[(size_t)NN * GK];
__device__ __nv_bfloat16 g_h1l[(size_t)NN * GK];
__device__ __nv_bfloat16 g_h2h[(size_t)NN * GK];
__device__ __nv_bfloat16 g_h2l[(size_t)NN * GK];
__device__ __nv_bfloat16 g_w1h[(size_t)384 * GK];
__device__ __nv_bfloat16 g_w1l[(size_t)384 * GK];
__device__ __nv_bfloat16 g_w2h[(size_t)256 * GK];
__device__ __nv_bfloat16 g_w2l[(size_t)256 * GK];
__device__ __nv_bfloat16 g_w3h[(size_t)256 * GK];
__device__ __nv_bfloat16 g_w3l[(size_t)256 * GK];
__device__ float g_bias1[384];
__device__ float g_bias2[256];
__device__ float g_bias3[256];
__device__ int   g_deg[NN];
__device__ int   g_rowptr[NN + 1];
__device__ int   g_pos[NN];
__device__ int   g_adj[EE];

__device__ __forceinline__ uint32_t smem_u32(const void* p) {
    uint32_t a;
    asm("{ .reg .u64 t; cvta.to.shared.u64 t, %1; cvt.u32.u64 %0, t; }" : "=r"(a) : "l"(p));
    return a;
}
__device__ __forceinline__ void cp16(uint32_t dst, const void* src, bool valid) {
    asm volatile("cp.async.cg.shared.global [%0], [%1], 16, %2;"
                 :: "r"(dst), "l"(src), "r"(valid ? 16 : 0));
}

// ---------------- CSR build ----------------
__global__ void zero_deg() {
    int i = blockIdx.x * blockDim.x + threadIdx.x;
    if (i < NN) g_deg[i] = 0;
}
__global__ void hist_dst(const int* __restrict__ ei) {
    int i = blockIdx.x * blockDim.x + threadIdx.x;
    if (i < EE) atomicAdd(&g_deg[ei[EE + i]], 1);
}
__global__ void scan_deg() {
    __shared__ int ssum[1024];
    const int CH = 49;
    int t = threadIdx.x;
    int base = t * CH;
    int s = 0;
#pragma unroll 1
    for (int i = 0; i < CH; i++) { int idx = base + i; if (idx < NN) s += g_deg[idx]; }
    ssum[t] = s;
    __syncthreads();
    for (int off = 1; off < 1024; off <<= 1) {
        int v = (t >= off) ? ssum[t - off] : 0;
        __syncthreads();
        ssum[t] += v;
        __syncthreads();
    }
    int run = (t == 0) ? 0 : ssum[t - 1];
#pragma unroll 1
    for (int i = 0; i < CH; i++) {
        int idx = base + i;
        if (idx < NN) { g_rowptr[idx] = run; g_pos[idx] = run; run += g_deg[idx]; }
    }
    if (t == 0) g_rowptr[NN] = EE;
}
__global__ void scatter_edges(const int* __restrict__ ei) {
    int i = blockIdx.x * blockDim.x + threadIdx.x;
    if (i >= EE) return;
    int s = ei[i];
    int d = ei[EE + i];
    int p = atomicAdd(&g_pos[d], 1);
    g_adj[p] = s;
}

// ---------------- bf16 split helpers ----------------
__device__ __forceinline__ void split_bf(float v, __nv_bfloat16& h, __nv_bfloat16& l) {
    h = __float2bfloat16_rn(v);
    l = __float2bfloat16_rn(v - __bfloat162float(h));
}

__global__ void convert_x(const float* __restrict__ x) {
    int i = blockIdx.x * blockDim.x + threadIdx.x;
    if (i >= NN * 32) return;
    int row = i >> 5, c4 = (i & 31) * 4;
    __nv_bfloat16 h[4], l[4];
#pragma unroll
    for (int q = 0; q < 4; q++) {
        int k = c4 + q;
        float v = (k < FIN) ? x[(size_t)row * FIN + k] : 0.f;
        split_bf(v, h[q], l[q]);
    }
    *(uint2*)&g_xh[(size_t)row * GK + c4] = *(uint2*)h;
    *(uint2*)&g_xl[(size_t)row * GK + c4] = *(uint2*)l;
}

__global__ void pack_w(const float* __restrict__ w1s, const float* __restrict__ w1d,
                       const float* __restrict__ r0w, const float* __restrict__ r0b,
                       const float* __restrict__ b1,
                       const float* __restrict__ w2s, const float* __restrict__ w2d,
                       const float* __restrict__ w3s, const float* __restrict__ w3d,
                       const float* __restrict__ r2w, const float* __restrict__ r2b,
                       const float* __restrict__ b3)
{
    const int S1 = 384 * GK, S2 = 256 * GK, S3 = 256 * GK;
    int i = blockIdx.x * blockDim.x + threadIdx.x;
    if (i < S1) {
        int n = i / GK, k = i % GK;
        float v = 0.f;
        if (k < FIN) {
            if (n < 128)      v = w1s[k * 128 + n];
            else if (n < 256) v = w1d[k * 128 + (n - 128)];
            else              v = r0w[k * 128 + (n - 256)];
        }
        split_bf(v, g_w1h[i], g_w1l[i]);
        return;
    }
    i -= S1;
    if (i < S2) {
        int n = i / GK, k = i % GK;
        float v = (n < 128) ? w2s[k * 128 + n] : w2d[k * 128 + (n - 128)];
        split_bf(v, g_w2h[i], g_w2l[i]);
        return;
    }
    i -= S2;
    if (i < S3) {
        int n = i / GK, k = i % GK;
        float v = 0.f;
        if (n < 47)                  v = w3s[k * 47 + n];
        else if (n >= 48 && n < 95)  v = w3d[k * 47 + (n - 48)];
        else if (n >= 96 && n < 143) v = r2w[k * 47 + (n - 96)];
        split_bf(v, g_w3h[i], g_w3l[i]);
        return;
    }
    i -= S3;
    if (i < 384) { g_bias1[i] = (i >= 256) ? (r0b[i - 256] + b1[i - 256]) : 0.f; return; }
    i -= 384;
    if (i < 256) { g_bias2[i] = 0.f; return; }
    i -= 256;
    if (i < 256) { g_bias3[i] = (i >= 96 && i < 143) ? (r2b[i - 96] + b3[i - 96]) : 0.f; return; }
}

// ---------------- mma.sync GEMM: C[M, Ntot] = (Ah+Al) @ (Bh+Bl)^T + bias --------------
// CTA tile 64x128, full K=128 in SMEM (96 KB -> 2 CTAs/SM), cp.async loads,
// double-buffered ldmatrix fragment prefetch across the 8 k-steps.

#define OFF_AH 0
#define OFF_AL 16384
#define OFF_BH 32768
#define OFF_BL 65536
#define SM_GEMM 98304

__device__ __forceinline__ uint32_t sw_off(int row, int chunk) {
    return (uint32_t)(row * 256 + ((chunk ^ (row & 7)) << 4));
}
__device__ __forceinline__ void ldsm_x4(uint32_t addr, uint32_t* r) {
    asm volatile("ldmatrix.sync.aligned.x4.m8n8.shared.b16 {%0,%1,%2,%3}, [%4];"
                 : "=r"(r[0]), "=r"(r[1]), "=r"(r[2]), "=r"(r[3]) : "r"(addr));
}
__device__ __forceinline__ void mma_bf16(float* c, const uint32_t* a, const uint32_t* b) {
    asm volatile("mma.sync.aligned.m16n8k16.row.col.f32.bf16.bf16.f32 "
                 "{%0,%1,%2,%3}, {%4,%5,%6,%7}, {%8,%9}, {%0,%1,%2,%3};"
                 : "+f"(c[0]), "+f"(c[1]), "+f"(c[2]), "+f"(c[3])
                 : "r"(a[0]), "r"(a[1]), "r"(a[2]), "r"(a[3]), "r"(b[0]), "r"(b[1]));
}

__global__ void __launch_bounds__(256, 2)
gemm_mma(const __nv_bfloat16* __restrict__ Ah, const __nv_bfloat16* __restrict__ Al,
         const __nv_bfloat16* __restrict__ Bh, const __nv_bfloat16* __restrict__ Bl,
         const float* __restrict__ bias, float* __restrict__ C, int M, int Ntot, int ldc)
{
    extern __shared__ char smem[];
    const uint32_t sb = smem_u32(smem);

    const int tid = threadIdx.x;
    const int wid = tid >> 5, lane = tid & 31;
    const int brow = blockIdx.y * 64;
    const int bcol = blockIdx.x * 128;

    // ---- async loads: A (64 rows) hi/lo, B (128 rows) hi/lo ----
    for (int i = tid; i < 1024; i += 256) {
        int r = i >> 4, kc = i & 15;
        uint32_t so = sw_off(r, kc);
        int gr = brow + r;
        bool v = gr < M;
        const char* pa = (const char*)(Ah + (size_t)gr * GK) + kc * 16;
        const char* pl = (const char*)(Al + (size_t)gr * GK) + kc * 16;
        cp16(sb + OFF_AH + so, v ? pa : (const char*)Ah, v);
        cp16(sb + OFF_AL + so, v ? pl : (const char*)Al, v);
    }
    for (int i = tid; i < 2048; i += 256) {
        int r = i >> 4, kc = i & 15;
        uint32_t so = sw_off(r, kc);
        int gn = bcol + r;                      // B pre-padded: no guard
        cp16(sb + OFF_BH + so, (const char*)(Bh + (size_t)gn * GK) + kc * 16, true);
        cp16(sb + OFF_BL + so, (const char*)(Bl + (size_t)gn * GK) + kc * 16, true);
    }
    asm volatile("cp.async.commit_group;" ::: "memory");
    asm volatile("cp.async.wait_group 0;" ::: "memory");
    __syncthreads();

    const int wm = (wid >> 2) * 32;             // 0 / 32
    const int wn = (wid & 3) * 32;              // 0,32,64,96

    float acc[2][4][4];
#pragma unroll
    for (int i = 0; i < 2; i++)
#pragma unroll
        for (int j = 0; j < 4; j++)
#pragma unroll
            for (int q = 0; q < 4; q++) acc[i][j][q] = 0.f;

    const int a_r  = (lane & 15);
    const int a_kc = (lane >> 4);
    const int b_r  = ((lane >> 4) & 1) * 8 + (lane & 7);
    const int b_kc = ((lane >> 3) & 1);

    uint32_t ah[2][2][4], al[2][2][4], bh[2][2][4], bl[2][2][4];  // [buf][frag][regs]

#define LOAD_FRAGS(KS, B)                                                 \
    do {                                                                  \
        _Pragma("unroll")                                                 \
        for (int ma = 0; ma < 2; ma++) {                                  \
            uint32_t off = sw_off(wm + ma * 16 + a_r, (KS) * 2 + a_kc);   \
            ldsm_x4(sb + OFF_AH + off, ah[B][ma]);                        \
            ldsm_x4(sb + OFF_AL + off, al[B][ma]);                        \
        }                                                                 \
        _Pragma("unroll")                                                 \
        for (int nb = 0; nb < 2; nb++) {                                  \
            uint32_t off = sw_off(wn + nb * 16 + b_r, (KS) * 2 + b_kc);   \
            ldsm_x4(sb + OFF_BH + off, bh[B][nb]);                        \
            ldsm_x4(sb + OFF_BL + off, bl[B][nb]);                        \
        }                                                                 \
    } while (0)

    LOAD_FRAGS(0, 0);
#pragma unroll
    for (int ks = 0; ks < 8; ks++) {
        const int cb = ks & 1;
        if (ks < 7) LOAD_FRAGS(ks + 1, cb ^ 1);
#pragma unroll
        for (int ma = 0; ma < 2; ma++)
#pragma unroll
            for (int na = 0; na < 4; na++) {
                const uint32_t* Bhf = &bh[cb][na >> 1][(na & 1) * 2];
                const uint32_t* Blf = &bl[cb][na >> 1][(na & 1) * 2];
                mma_bf16(acc[ma][na], ah[cb][ma], Bhf);
                mma_bf16(acc[ma][na], al[cb][ma], Bhf);
                mma_bf16(acc[ma][na], ah[cb][ma], Blf);
            }
    }
#undef LOAD_FRAGS

    // ---- epilogue ----
    const int gq = lane >> 2, tg = lane & 3;
#pragma unroll
    for (int ma = 0; ma < 2; ma++) {
        int row0 = brow + wm + ma * 16 + gq;
        int row1 = row0 + 8;
#pragma unroll
        for (int na = 0; na < 4; na++) {
            int col = bcol + wn + na * 8 + tg * 2;
            if (col >= Ntot) continue;
            float b0 = bias[col], b1 = bias[col + 1];
            if (row0 < M) {
                float2 o = {acc[ma][na][0] + b0, acc[ma][na][1] + b1};
                *(float2*)(C + (size_t)row0 * ldc + col) = o;
            }
            if (row1 < M) {
                float2 o = {acc[ma][na][2] + b0, acc[ma][na][3] + b1};
                *(float2*)(C + (size_t)row1 * ldc + col) = o;
            }
        }
    }
}

// ---------------- fused node kernel: 4 heads x 32 ch, warp per node ----------------
// Pair-unrolled online softmax: 2 gathers in flight, half the serial exp chain.
__global__ void __launch_bounds__(256)
gat_node4v(const float* __restrict__ xlxr, int ldin, int xroff,
           const float* __restrict__ res, int ldres,
           const float* __restrict__ att, const float* __restrict__ bias,
           const float* __restrict__ bng, const float* __restrict__ bnb,
           const float* __restrict__ bnm, const float* __restrict__ bnv,
           float* __restrict__ outbuf, int ldout,
           __nv_bfloat16* __restrict__ outh, __nv_bfloat16* __restrict__ outl)
{
    int d    = (blockIdx.x * blockDim.x + threadIdx.x) >> 5;
    int lane = threadIdx.x & 31;
    if (d >= NN) return;
    int c = lane * 4;

    const float4 xr4 = *(const float4*)(xlxr + (size_t)d * ldin + xroff + c);
    const float4 at4 = *(const float4*)(att + c);

#define LOGIT(xv, vout)                                                       \
    do {                                                                      \
        float t0 = (xv).x + xr4.x; t0 = (t0 > 0.f) ? t0 : NEG * t0;           \
        float t1 = (xv).y + xr4.y; t1 = (t1 > 0.f) ? t1 : NEG * t1;           \
        float t2 = (xv).z + xr4.z; t2 = (t2 > 0.f) ? t2 : NEG * t2;           \
        float t3 = (xv).w + xr4.w; t3 = (t3 > 0.f) ? t3 : NEG * t3;           \
        float vv = t0 * at4.x + t1 * at4.y + t2 * at4.z + t3 * at4.w;         \
        vv += __shfl_xor_sync(0xffffffffu, vv, 1);                            \
        vv += __shfl_xor_sync(0xffffffffu, vv, 2);                            \
        vv += __shfl_xor_sync(0xffffffffu, vv, 4);                            \
        (vout) = vv;                                                          \
    } while (0)

    int beg = g_rowptr[d], end = g_rowptr[d + 1];

    // self loop initializes the state (w = 1)
    float4 acc = *(const float4*)(xlxr + (size_t)d * ldin + c);
    float m;
    LOGIT(acc, m);
    float den = 1.f;

    int j = beg;
    for (; j + 1 < end; j += 2) {
        int sa = g_adj[j], sb2 = g_adj[j + 1];
        float4 xa = *(const float4*)(xlxr + (size_t)sa * ldin + c);
        float4 xb = *(const float4*)(xlxr + (size_t)sb2 * ldin + c);
        float va, vb;
        LOGIT(xa, va);
        LOGIT(xb, vb);
        float mn = fmaxf(m, fmaxf(va, vb));
        float sc = __expf(m - mn);
        float wa = __expf(va - mn);
        float wb = __expf(vb - mn);
        den = den * sc + wa + wb;
        acc.x = acc.x * sc + wa * xa.x + wb * xb.x;
        acc.y = acc.y * sc + wa * xa.y + wb * xb.y;
        acc.z = acc.z * sc + wa * xa.z + wb * xb.z;
        acc.w = acc.w * sc + wa * xa.w + wb * xb.w;
        m = mn;
    }
    if (j < end) {
        int sa = g_adj[j];
        float4 xa = *(const float4*)(xlxr + (size_t)sa * ldin + c);
        float va;
        LOGIT(xa, va);
        float mn = fmaxf(m, va);
        float sc = __expf(m - mn);
        float wa = __expf(va - mn);
        den = den * sc + wa;
        acc.x = acc.x * sc + wa * xa.x;
        acc.y = acc.y * sc + wa * xa.y;
        acc.z = acc.z * sc + wa * xa.z;
        acc.w = acc.w * sc + wa * xa.w;
        m = mn;
    }
#undef LOGIT

    float inv = 1.f / den;
    float4 o;
    o.x = acc.x * inv; o.y = acc.y * inv; o.z = acc.z * inv; o.w = acc.w * inv;
    if (bias) {
        float4 bv = *(const float4*)(bias + c);
        o.x += bv.x; o.y += bv.y; o.z += bv.z; o.w += bv.w;
    }
    float4 rv = *(const float4*)(res + (size_t)d * ldres + c);
    o.x += rv.x; o.y += rv.y; o.z += rv.z; o.w += rv.w;

    float4 mm = *(const float4*)(bnm + c);
    float4 vv = *(const float4*)(bnv + c);
    float4 gg = *(const float4*)(bng + c);
    float4 bb = *(const float4*)(bnb + c);
    o.x = fmaxf((o.x - mm.x) * rsqrtf(vv.x + BNEPS) * gg.x + bb.x, 0.f);
    o.y = fmaxf((o.y - mm.y) * rsqrtf(vv.y + BNEPS) * gg.y + bb.y, 0.f);
    o.z = fmaxf((o.z - mm.z) * rsqrtf(vv.z + BNEPS) * gg.z + bb.z, 0.f);
    o.w = fmaxf((o.w - mm.w) * rsqrtf(vv.w + BNEPS) * gg.w + bb.w, 0.f);
    *(float4*)(outbuf + (size_t)d * ldout + c) = o;

    __nv_bfloat16 hh[4], ll[4];
    split_bf(o.x, hh[0], ll[0]);
    split_bf(o.y, hh[1], ll[1]);
    split_bf(o.z, hh[2], ll[2]);
    split_bf(o.w, hh[3], ll[3]);
    *(uint2*)&outh[(size_t)d * GK + c] = *(uint2*)hh;
    *(uint2*)&outl[(size_t)d * GK + c] = *(uint2*)ll;
}

// ---------------- fused node kernel: 1 head x 47 ch (warp per node) ----------------
__global__ void __launch_bounds__(256)
gat_node1(const float* __restrict__ cat, const float* __restrict__ att,
          const float* __restrict__ bng, const float* __restrict__ bnb,
          const float* __restrict__ bnm, const float* __restrict__ bnv,
          float* __restrict__ outbuf)
{
    int d    = (blockIdx.x * blockDim.x + threadIdx.x) >> 5;
    int lane = threadIdx.x & 31;
    if (d >= NN) return;

    int c0 = lane;
    int c1 = lane + 32;
    bool has1 = (c1 < FOUT);

    const float* rowd = cat + (size_t)d * NC3;
    float xr0 = rowd[48 + c0];
    float xr1 = has1 ? rowd[48 + c1] : 0.f;
    float a0  = att[c0];
    float a1  = has1 ? att[c1] : 0.f;

#define LOGIT1(x0, x1, vout)                                                  \
    do {                                                                      \
        float t0 = (x0) + xr0; t0 = (t0 > 0.f) ? t0 : NEG * t0;               \
        float t1 = (x1) + xr1; t1 = (t1 > 0.f) ? t1 : NEG * t1;               \
        float vv = t0 * a0 + t1 * a1;                                         \
        _Pragma("unroll")                                                     \
        for (int o = 16; o; o >>= 1) vv += __shfl_xor_sync(0xffffffffu, vv, o); \
        (vout) = vv;                                                          \
    } while (0)

    int beg = g_rowptr[d], end = g_rowptr[d + 1];

    // self loop
    float acc0 = rowd[c0];
    float acc1 = has1 ? rowd[c1] : 0.f;
    float m;
    LOGIT1(acc0, acc1, m);
    float den = 1.f;

    int j = beg;
    for (; j + 1 < end; j += 2) {
        const float* ra = cat + (size_t)g_adj[j] * NC3;
        const float* rb = cat + (size_t)g_adj[j + 1] * NC3;
        float xa0 = ra[c0], xa1 = has1 ? ra[c1] : 0.f;
        float xb0 = rb[c0], xb1 = has1 ? rb[c1] : 0.f;
        float va, vb;
        LOGIT1(xa0, xa1, va);
        LOGIT1(xb0, xb1, vb);
        float mn = fmaxf(m, fmaxf(va, vb));
        float sc = __expf(m - mn);
        float wa = __expf(va - mn);
        float wb = __expf(vb - mn);
        den  = den  * sc + wa + wb;
        acc0 = acc0 * sc + wa * xa0 + wb * xb0;
        acc1 = acc1 * sc + wa * xa1 + wb * xb1;
        m = mn;
    }
    if (j < end) {
        const float* ra = cat + (size_t)g_adj[j] * NC3;
        float xa0 = ra[c0], xa1 = has1 ? ra[c1] : 0.f;
        float va;
        LOGIT1(xa0, xa1, va);
        float mn = fmaxf(m, va);
        float sc = __expf(m - mn);
        float wa = __expf(va - mn);
        den  = den  * sc + wa;
        acc0 = acc0 * sc + wa * xa0;
        acc1 = acc1 * sc + wa * xa1;
        m = mn;
    }
#undef LOGIT1

    float inv = 1.f / den;
    {
        float val = acc0 * inv + rowd[96 + c0];
        val = (val - bnm[c0]) * rsqrtf(bnv[c0] + BNEPS) * bng[c0] + bnb[c0];
        outbuf[(size_t)d * FOUT + c0] = val;
    }
    if (has1) {
        float val = acc1 * inv + rowd[96 + c1];
        val = (val - bnm[c1]) * rsqrtf(bnv[c1] + BNEPS) * bng[c1] + bnb[c1];
        outbuf[(size_t)d * FOUT + c1] = val;
    }
}

// ---------------- launch ----------------
static inline int cdiv(int a, int b) { return (a + b - 1) / b; }

extern "C" void kernel_launch(void* const* d_in, const int* in_sizes, int n_in,
                              void* d_out, int out_size)
{
    const float* x      = (const float*)d_in[0];
    const int*   ei     = (const int*)  d_in[1];
    const float* w1_src = (const float*)d_in[2];
    const float* w1_dst = (const float*)d_in[3];
    const float* att1   = (const float*)d_in[4];
    const float* b1     = (const float*)d_in[5];
    const float* bn1_g  = (const float*)d_in[6];
    const float* bn1_b  = (const float*)d_in[7];
    const float* bn1_m  = (const float*)d_in[8];
    const float* bn1_v  = (const float*)d_in[9];
    const float* res0_w = (const float*)d_in[10];
    const float* res0_b = (const float*)d_in[11];
    const float* w2_src = (const float*)d_in[12];
    const float* w2_dst = (const float*)d_in[13];
    const float* att2   = (const float*)d_in[14];
    const float* b2     = (const float*)d_in[15];
    const float* bn2_g  = (const float*)d_in[16];
    const float* bn2_b  = (const float*)d_in[17];
    const float* bn2_m  = (const float*)d_in[18];
    const float* bn2_v  = (const float*)d_in[19];
    const float* w3_src = (const float*)d_in[20];
    const float* w3_dst = (const float*)d_in[21];
    const float* att3   = (const float*)d_in[22];
    const float* b3     = (const float*)d_in[23];
    const float* bn3_g  = (const float*)d_in[24];
    const float* bn3_b  = (const float*)d_in[25];
    const float* bn3_m  = (const float*)d_in[26];
    const float* bn3_v  = (const float*)d_in[27];
    const float* res2_w = (const float*)d_in[28];
    const float* res2_b = (const float*)d_in[29];
    float* out = (float*)d_out;

    float *cat1, *cat2, *cat3, *h1, *h2, *bi1, *bi2, *bi3;
    __nv_bfloat16 *xh, *xl, *h1h, *h1l, *h2h, *h2l, *w1h, *w1l, *w2h, *w2l, *w3h, *w3l;
    cudaGetSymbolAddress((void**)&cat1, g_cat1);
    cudaGetSymbolAddress((void**)&cat2, g_cat2);
    cudaGetSymbolAddress((void**)&cat3, g_cat3);
    cudaGetSymbolAddress((void**)&h1, g_h1);
    cudaGetSymbolAddress((void**)&h2, g_h2);
    cudaGetSymbolAddress((void**)&xh, g_xh);
    cudaGetSymbolAddress((void**)&xl, g_xl);
    cudaGetSymbolAddress((void**)&h1h, g_h1h);
    cudaGetSymbolAddress((void**)&h1l, g_h1l);
    cudaGetSymbolAddress((void**)&h2h, g_h2h);
    cudaGetSymbolAddress((void**)&h2l, g_h2l);
    cudaGetSymbolAddress((void**)&w1h, g_w1h);
    cudaGetSymbolAddress((void**)&w1l, g_w1l);
    cudaGetSymbolAddress((void**)&w2h, g_w2h);
    cudaGetSymbolAddress((void**)&w2l, g_w2l);
    cudaGetSymbolAddress((void**)&w3h, g_w3h);
    cudaGetSymbolAddress((void**)&w3l, g_w3l);
    cudaGetSymbolAddress((void**)&bi1, g_bias1);
    cudaGetSymbolAddress((void**)&bi2, g_bias2);
    cudaGetSymbolAddress((void**)&bi3, g_bias3);

    cudaFuncSetAttribute(gemm_mma, cudaFuncAttributeMaxDynamicSharedMemorySize, SM_GEMM);

    const int MT = cdiv(NN, 64);      // 782 M-tiles
    const int NB = cdiv(NN, 8);

    // launch order: gemm L1 at index 3 (ncu capture slot)
    convert_x<<<cdiv(NN * 32, 256), 256>>>(x);                                  // 0
    pack_w<<<cdiv((384 + 256 + 256) * GK + 384 + 256 + 256, 256), 256>>>(       // 1
        w1_src, w1_dst, res0_w, res0_b, b1, w2_src, w2_dst,
        w3_src, w3_dst, res2_w, res2_b, b3);
    zero_deg<<<cdiv(NN, 256), 256>>>();                                         // 2
    gemm_mma<<<dim3(3, MT), 256, SM_GEMM>>>(xh, xl, w1h, w1l, bi1, cat1, NN, NC1, NC1);  // 3
    hist_dst<<<cdiv(EE, 256), 256>>>(ei);                                       // 4
    scan_deg<<<1, 1024>>>();                                                    // 5
    scatter_edges<<<cdiv(EE, 256), 256>>>(ei);                                  // 6

    // ===== layer 1 node phase =====
    gat_node4v<<<NB, 256>>>(cat1, NC1, 128, cat1 + 256, NC1, att1, nullptr,
                            bn1_g, bn1_b, bn1_m, bn1_v, h1, W1C, h1h, h1l);

    // ===== layer 2 (identity residual) =====
    gemm_mma<<<dim3(2, MT), 256, SM_GEMM>>>(h1h, h1l, w2h, w2l, bi2, cat2, NN, NC2, NC2);
    gat_node4v<<<NB, 256>>>(cat2, NC2, 128, h1, W1C, att2, b2,
                            bn2_g, bn2_b, bn2_m, bn2_v, h2, W1C, h2h, h2l);

    // ===== layer 3 (heads=1, 47 out) =====
    gemm_mma<<<dim3(2, MT), 256, SM_GEMM>>>(h2h, h2l, w3h, w3l, bi3, cat3, NN, NC3, NC3);
    gat_node1<<<NB, 256>>>(cat3, att3, bn3_g, bn3_b, bn3_m, bn3_v, out);
}